// round 1
// baseline (speedup 1.0000x reference)
#include <cuda_runtime.h>
#include <cstdint>

// Problem constants
#define BATCH 4
#define S_LEN 2048
#define HEADS 16
#define DH    64
#define DM    1024
#define MROWS (BATCH * S_LEN)   // 8192

// Device scratch (no allocation allowed) — 4 x 32MB
__device__ float g_Q[BATCH * HEADS * S_LEN * DH];   // [B,H,S,Dh]
__device__ float g_K[BATCH * HEADS * S_LEN * DH];
__device__ float g_V[BATCH * HEADS * S_LEN * DH];
__device__ float g_A[MROWS * DM];                   // attention out as [B,S,H,Dh] = [8192,1024]

// ---------------------------------------------------------------------------
// GEMM: C = A @ W^T  where A is [M=8192, K=1024] row-major, W is [N=1024, K=1024]
// row-major (nn.Linear convention). 128x128 tile, BK=8, 256 threads, 8x8 micro.
// permute=1: scatter output into [B,H,S,Dh]; permute=0: plain [M,N] row-major.
// ---------------------------------------------------------------------------
__global__ __launch_bounds__(256) void sgemm_tn(const float* __restrict__ A,
                                                const float* __restrict__ W,
                                                float* __restrict__ C,
                                                int permute)
{
    const int Kd = DM;
    const int N  = DM;

    __shared__ float As[8][128];
    __shared__ float Bs[8][128];

    const int tid = threadIdx.x;
    const int ty  = tid >> 4;     // 0..15
    const int tx  = tid & 15;     // 0..15

    const int mBase = blockIdx.y * 128;
    const int nBase = blockIdx.x * 128;

    const int lm  = tid >> 1;          // 0..127
    const int lk4 = (tid & 1) * 4;     // 0 or 4

    const float* Aptr = A + (size_t)(mBase + lm) * Kd + lk4;
    const float* Wptr = W + (size_t)(nBase + lm) * Kd + lk4;

    float c[8][8];
#pragma unroll
    for (int i = 0; i < 8; i++)
#pragma unroll
        for (int j = 0; j < 8; j++) c[i][j] = 0.0f;

    for (int kb = 0; kb < Kd; kb += 8) {
        float4 av = *reinterpret_cast<const float4*>(Aptr + kb);
        float4 wv = *reinterpret_cast<const float4*>(Wptr + kb);
        As[lk4 + 0][lm] = av.x;
        As[lk4 + 1][lm] = av.y;
        As[lk4 + 2][lm] = av.z;
        As[lk4 + 3][lm] = av.w;
        Bs[lk4 + 0][lm] = wv.x;
        Bs[lk4 + 1][lm] = wv.y;
        Bs[lk4 + 2][lm] = wv.z;
        Bs[lk4 + 3][lm] = wv.w;
        __syncthreads();

#pragma unroll
        for (int k = 0; k < 8; k++) {
            float4 a0 = *reinterpret_cast<const float4*>(&As[k][ty * 4]);
            float4 a1 = *reinterpret_cast<const float4*>(&As[k][ty * 4 + 64]);
            float4 b0 = *reinterpret_cast<const float4*>(&Bs[k][tx * 4]);
            float4 b1 = *reinterpret_cast<const float4*>(&Bs[k][tx * 4 + 64]);
            float ar[8] = {a0.x, a0.y, a0.z, a0.w, a1.x, a1.y, a1.z, a1.w};
            float br[8] = {b0.x, b0.y, b0.z, b0.w, b1.x, b1.y, b1.z, b1.w};
#pragma unroll
            for (int i = 0; i < 8; i++)
#pragma unroll
                for (int j = 0; j < 8; j++)
                    c[i][j] = fmaf(ar[i], br[j], c[i][j]);
        }
        __syncthreads();
    }

    // Epilogue
#pragma unroll
    for (int ii = 0; ii < 8; ii++) {
        int m = mBase + ty * 4 + (ii & 3) + ((ii >= 4) ? 64 : 0);
#pragma unroll
        for (int g = 0; g < 2; g++) {
            int n = nBase + g * 64 + tx * 4;
            float4 v = make_float4(c[ii][g * 4 + 0], c[ii][g * 4 + 1],
                                   c[ii][g * 4 + 2], c[ii][g * 4 + 3]);
            if (!permute) {
                *reinterpret_cast<float4*>(&C[(size_t)m * N + n]) = v;
            } else {
                int b = m >> 11;         // m / 2048
                int s = m & 2047;
                int h = n >> 6;          // n / 64
                int d = n & 63;
                size_t addr = ((size_t)((b * HEADS + h) * S_LEN) + s) * DH + d;
                *reinterpret_cast<float4*>(&C[addr]) = v;
            }
        }
    }
}

// ---------------------------------------------------------------------------
// Flash attention (fp32, causal, online softmax).
// Grid: (S/64 = 32 query tiles, B*H = 64). Block 256 threads (16x16).
// Thread (ty,tx) owns a 4x4 microtile: rows q = 4*ty+i, cols k (scores) or
// cols d (output) = 4*tx+j.
// SMEM (dynamic): Qt[64][68] (d-major), KP[64][68] (K d-major, reused as P^T
// k-major), Vs[64][64].
// ---------------------------------------------------------------------------
#define QSTR 68
__global__ __launch_bounds__(256) void flash_attn_kernel()
{
    extern __shared__ float sm[];
    float* Qt = sm;                     // [64][68]  Qt[d][q]
    float* KP = sm + 64 * QSTR;         // [64][68]  Kt[d][k]  then  Pt[k][q]
    float* Vs = sm + 2 * 64 * QSTR;     // [64][64]  Vs[k][d]

    const int tid = threadIdx.x;
    const int ty  = tid >> 4;
    const int tx  = tid & 15;

    const int bh = blockIdx.y;          // b*16 + h
    const int qt = blockIdx.x;          // query tile

    const float* Qg = g_Q + (size_t)bh * S_LEN * DH + (size_t)qt * 64 * DH;
    const float* Kg = g_K + (size_t)bh * S_LEN * DH;
    const float* Vg = g_V + (size_t)bh * S_LEN * DH;

    // Load Q tile (transposed, pre-scaled by 1/sqrt(Dh)=0.125)
    for (int idx = tid; idx < 64 * 64; idx += 256) {
        int q = idx >> 6, d = idx & 63;
        Qt[d * QSTR + q] = Qg[(size_t)q * DH + d] * 0.125f;
    }

    float m_i[4], l_i[4], acc[4][4];
#pragma unroll
    for (int i = 0; i < 4; i++) {
        m_i[i] = -1e30f;
        l_i[i] = 0.0f;
#pragma unroll
        for (int j = 0; j < 4; j++) acc[i][j] = 0.0f;
    }

    for (int kt = 0; kt <= qt; ++kt) {
        const float* Kb = Kg + (size_t)kt * 64 * DH;
        const float* Vb = Vg + (size_t)kt * 64 * DH;

        // Load K tile transposed, V tile straight
        for (int idx = tid; idx < 64 * 64; idx += 256) {
            int k = idx >> 6, d = idx & 63;
            KP[d * QSTR + k] = Kb[idx];
        }
        for (int idx = tid * 4; idx < 64 * 64; idx += 1024) {
            *reinterpret_cast<float4*>(&Vs[idx]) =
                *reinterpret_cast<const float4*>(&Vb[idx]);
        }
        __syncthreads();

        // Scores S = Q K^T (4x4 per thread)
        float s[4][4];
#pragma unroll
        for (int i = 0; i < 4; i++)
#pragma unroll
            for (int j = 0; j < 4; j++) s[i][j] = 0.0f;

#pragma unroll 8
        for (int d = 0; d < 64; d++) {
            float4 qa = *reinterpret_cast<const float4*>(&Qt[d * QSTR + ty * 4]);
            float4 kb = *reinterpret_cast<const float4*>(&KP[d * QSTR + tx * 4]);
            float qr[4] = {qa.x, qa.y, qa.z, qa.w};
            float kr[4] = {kb.x, kb.y, kb.z, kb.w};
#pragma unroll
            for (int i = 0; i < 4; i++)
#pragma unroll
                for (int j = 0; j < 4; j++)
                    s[i][j] = fmaf(qr[i], kr[j], s[i][j]);
        }

        // Causal mask (diagonal tile only)
        if (kt == qt) {
#pragma unroll
            for (int i = 0; i < 4; i++)
#pragma unroll
                for (int j = 0; j < 4; j++)
                    if (tx * 4 + j > ty * 4 + i) s[i][j] = -1e30f;
        }

        // Online softmax update
        float p[4][4];
#pragma unroll
        for (int i = 0; i < 4; i++) {
            float mx = fmaxf(fmaxf(s[i][0], s[i][1]), fmaxf(s[i][2], s[i][3]));
#pragma unroll
            for (int off = 8; off; off >>= 1)
                mx = fmaxf(mx, __shfl_xor_sync(0xffffffffu, mx, off, 16));
            float mnew = fmaxf(m_i[i], mx);
            float sc = __expf(m_i[i] - mnew);
            float ls = 0.0f;
#pragma unroll
            for (int j = 0; j < 4; j++) {
                p[i][j] = __expf(s[i][j] - mnew);
                ls += p[i][j];
            }
#pragma unroll
            for (int off = 8; off; off >>= 1)
                ls += __shfl_xor_sync(0xffffffffu, ls, off, 16);
            l_i[i] = l_i[i] * sc + ls;
#pragma unroll
            for (int j = 0; j < 4; j++) acc[i][j] *= sc;
            m_i[i] = mnew;
        }

        __syncthreads();   // done reading KP as K

        // Write P^T into KP: Pt[k][q]
#pragma unroll
        for (int j = 0; j < 4; j++)
#pragma unroll
            for (int i = 0; i < 4; i++)
                KP[(tx * 4 + j) * QSTR + ty * 4 + i] = p[i][j];
        __syncthreads();

        // acc += P V
#pragma unroll 8
        for (int kk = 0; kk < 64; kk++) {
            float4 pa = *reinterpret_cast<const float4*>(&KP[kk * QSTR + ty * 4]);
            float4 vb = *reinterpret_cast<const float4*>(&Vs[kk * 64 + tx * 4]);
            float pr[4] = {pa.x, pa.y, pa.z, pa.w};
            float vr[4] = {vb.x, vb.y, vb.z, vb.w};
#pragma unroll
            for (int i = 0; i < 4; i++)
#pragma unroll
                for (int j = 0; j < 4; j++)
                    acc[i][j] = fmaf(pr[i], vr[j], acc[i][j]);
        }
        __syncthreads();   // before next tile overwrites KP/Vs
    }

    // Epilogue: out[b][s][h][d] = acc / l
    const int b = bh >> 4;
    const int h = bh & 15;
#pragma unroll
    for (int i = 0; i < 4; i++) {
        float rl = 1.0f / l_i[i];
        int sIdx = qt * 64 + ty * 4 + i;
        float4 v = make_float4(acc[i][0] * rl, acc[i][1] * rl,
                               acc[i][2] * rl, acc[i][3] * rl);
        size_t addr = (((size_t)(b * S_LEN + sIdx)) * HEADS + h) * DH + tx * 4;
        *reinterpret_cast<float4*>(&g_A[addr]) = v;
    }
}

// ---------------------------------------------------------------------------
// Launch
// ---------------------------------------------------------------------------
extern "C" void kernel_launch(void* const* d_in, const int* in_sizes, int n_in,
                              void* d_out, int out_size)
{
    const float* X  = (const float*)d_in[0];
    const float* WQ = (const float*)d_in[1];
    const float* WK = (const float*)d_in[2];
    const float* WV = (const float*)d_in[3];
    const float* WO = (const float*)d_in[4];
    float* out = (float*)d_out;

    float *Qp, *Kp, *Vp, *Ap;
    cudaGetSymbolAddress((void**)&Qp, g_Q);
    cudaGetSymbolAddress((void**)&Kp, g_K);
    cudaGetSymbolAddress((void**)&Vp, g_V);
    cudaGetSymbolAddress((void**)&Ap, g_A);

    const int smem_flash = (2 * 64 * QSTR + 64 * 64) * sizeof(float);  // 51200 B
    cudaFuncSetAttribute(flash_attn_kernel,
                         cudaFuncAttributeMaxDynamicSharedMemorySize, smem_flash);

    dim3 gGemm(DM / 128, MROWS / 128);   // (8, 64)

    sgemm_tn<<<gGemm, 256>>>(X, WQ, Qp, 1);
    sgemm_tn<<<gGemm, 256>>>(X, WK, Kp, 1);
    sgemm_tn<<<gGemm, 256>>>(X, WV, Vp, 1);

    dim3 gFlash(S_LEN / 64, BATCH * HEADS);  // (32, 64)
    flash_attn_kernel<<<gFlash, 256, smem_flash>>>();

    sgemm_tn<<<gGemm, 256>>>(Ap, WO, out, 0);
}

// round 3
// speedup vs baseline: 1.6242x; 1.6242x over previous
#include <cuda_runtime.h>
#include <cuda_bf16.h>
#include <cstdint>

// Problem constants
#define BATCH 4
#define S_LEN 2048
#define HEADS 16
#define DH    64
#define DM    1024
#define MROWS (BATCH * S_LEN)   // 8192

// ---------------------------------------------------------------------------
// Device scratch (no allocation allowed)
// ---------------------------------------------------------------------------
__device__ float g_Q[BATCH * HEADS * S_LEN * DH];   // [B,H,S,Dh] fp32
__device__ float g_K[BATCH * HEADS * S_LEN * DH];
__device__ float g_V[BATCH * HEADS * S_LEN * DH];
__device__ float g_A[MROWS * DM];                   // attn out [B,S,H*Dh]

__device__ __nv_bfloat16 g_Xhi[MROWS * DM];
__device__ __nv_bfloat16 g_Xlo[MROWS * DM];
__device__ __nv_bfloat16 g_Ahi[MROWS * DM];
__device__ __nv_bfloat16 g_Alo[MROWS * DM];
__device__ __nv_bfloat16 g_Whi[4][DM * DM];
__device__ __nv_bfloat16 g_Wlo[4][DM * DM];

// ---------------------------------------------------------------------------
// PTX helpers (sm_80-era only: cp.async, ldmatrix, mma.sync — no tcgen05)
// ---------------------------------------------------------------------------
__device__ __forceinline__ uint32_t smem_to_u32(const void* p) {
    uint32_t a;
    asm("{ .reg .u64 t; cvta.to.shared.u64 t, %1; cvt.u32.u64 %0, t; }"
        : "=r"(a) : "l"(p));
    return a;
}

#define CP_ASYNC16(smem_u32, gptr) \
    asm volatile("cp.async.cg.shared.global [%0], [%1], 16;" \
                 :: "r"(smem_u32), "l"(__cvta_generic_to_global(gptr)) : "memory")
#define CP_COMMIT()  asm volatile("cp.async.commit_group;" ::: "memory")

#define LDSM_X4(r0, r1, r2, r3, addr) \
    asm volatile("ldmatrix.sync.aligned.m8n8.x4.shared.b16 {%0,%1,%2,%3}, [%4];" \
                 : "=r"(r0), "=r"(r1), "=r"(r2), "=r"(r3) : "r"(addr))

#define MMA_BF16(d, a, b) \
    asm volatile("mma.sync.aligned.m16n8k16.row.col.f32.bf16.bf16.f32 " \
                 "{%0,%1,%2,%3}, {%4,%5,%6,%7}, {%8,%9}, {%0,%1,%2,%3};" \
                 : "+f"((d)[0]), "+f"((d)[1]), "+f"((d)[2]), "+f"((d)[3]) \
                 : "r"((a)[0]), "r"((a)[1]), "r"((a)[2]), "r"((a)[3]), \
                   "r"((b)[0]), "r"((b)[1]))

#define SW128(off) ((off) ^ (((off) >> 3) & 0x70))

// ---------------------------------------------------------------------------
// fp32 -> (hi, lo) bf16 split
// ---------------------------------------------------------------------------
__global__ __launch_bounds__(256) void split_kernel(const float4* __restrict__ x,
                                                    __nv_bfloat162* __restrict__ hi2,
                                                    __nv_bfloat162* __restrict__ lo2,
                                                    int n4)
{
    for (int i = blockIdx.x * blockDim.x + threadIdx.x; i < n4;
         i += gridDim.x * blockDim.x) {
        float4 v = x[i];
        __nv_bfloat16 h0 = __float2bfloat16(v.x);
        __nv_bfloat16 h1 = __float2bfloat16(v.y);
        __nv_bfloat16 h2 = __float2bfloat16(v.z);
        __nv_bfloat16 h3 = __float2bfloat16(v.w);
        __nv_bfloat16 l0 = __float2bfloat16(v.x - __bfloat162float(h0));
        __nv_bfloat16 l1 = __float2bfloat16(v.y - __bfloat162float(h1));
        __nv_bfloat16 l2 = __float2bfloat16(v.z - __bfloat162float(h2));
        __nv_bfloat16 l3 = __float2bfloat16(v.w - __bfloat162float(h3));
        __nv_bfloat162 a, b, c, d;
        a.x = h0; a.y = h1; b.x = h2; b.y = h3;
        c.x = l0; c.y = l1; d.x = l2; d.y = l3;
        hi2[2 * i]     = a;
        hi2[2 * i + 1] = b;
        lo2[2 * i]     = c;
        lo2[2 * i + 1] = d;
    }
}

// ---------------------------------------------------------------------------
// HMMA GEMM:  C[M=8192, N=1024] = A[M,K=1024] @ W[N,K]^T
// split-bf16: D = Ahi*Whi + Ahi*Wlo + Alo*Whi, fp32 accumulate in registers.
// Tile 128x128, K-chunk 64 (one SW128 row), cp.async double-buffered.
// 8 warps: wm = wid&3 (32 rows), wn = wid>>2 (64 cols). Warp tile 32x64.
// permute=1: scatter C into [B,H,S,Dh]; permute=0: row-major [M,N].
// ---------------------------------------------------------------------------
#define TILE_B   16384          // one 128x64 bf16 tile in bytes (128B rows)
#define STAGE_B  (4 * TILE_B)   // Ahi, Alo, Whi, Wlo

__global__ __launch_bounds__(256) void tc_gemm(const __nv_bfloat16* __restrict__ Ahi,
                                               const __nv_bfloat16* __restrict__ Alo,
                                               const __nv_bfloat16* __restrict__ Whi,
                                               const __nv_bfloat16* __restrict__ Wlo,
                                               float* __restrict__ C,
                                               int permute)
{
    extern __shared__ __align__(1024) char smem[];
    const uint32_t sb = smem_to_u32(smem);
    const int tid  = threadIdx.x;
    const int wid  = tid >> 5;
    const int lane = tid & 31;

    const int mBase = blockIdx.y * 128;
    const int nBase = blockIdx.x * 128;

    const int wm = wid & 3;    // m sub-tile (32 rows)
    const int wn = wid >> 2;   // n sub-tile (64 cols)

    const char* srcs[4] = {
        (const char*)(Ahi + (size_t)mBase * DM),
        (const char*)(Alo + (size_t)mBase * DM),
        (const char*)(Whi + (size_t)nBase * DM),
        (const char*)(Wlo + (size_t)nBase * DM)
    };

    // ldmatrix per-lane addressing pieces
    const int l15   = lane & 15;               // row within 16-row ldsm tile
    const int khalf = ((lane >> 4) & 1) * 16;  // +16B for k+8 matrices

    float acc[2][8][4];
#pragma unroll
    for (int mt = 0; mt < 2; mt++)
#pragma unroll
        for (int nt = 0; nt < 8; nt++)
#pragma unroll
            for (int r = 0; r < 4; r++) acc[mt][nt][r] = 0.0f;

    // ---- stage loader (4 tiles x 16KB via cp.async) ----
    auto load_stage = [&](int ic, int buf) {
        const uint32_t stage = sb + buf * STAGE_B;
#pragma unroll
        for (int t = 0; t < 4; t++) {
            const char* src = srcs[t];
#pragma unroll
            for (int r = 0; r < 4; r++) {
                int unit = r * 256 + tid;     // 0..1023
                int row  = unit >> 3;         // 0..127
                int c16  = unit & 7;          // 0..7
                const char* g = src + (size_t)row * (DM * 2) + ic * 128 + c16 * 16;
                uint32_t so = stage + t * TILE_B + SW128(row * 128 + c16 * 16);
                CP_ASYNC16(so, g);
            }
        }
        CP_COMMIT();
    };

    load_stage(0, 0);

    for (int ic = 0; ic < 16; ic++) {
        if (ic < 15) load_stage(ic + 1, (ic + 1) & 1);
        if (ic < 15) asm volatile("cp.async.wait_group 1;" ::: "memory");
        else         asm volatile("cp.async.wait_group 0;" ::: "memory");
        __syncthreads();

        const uint32_t stage = sb + (ic & 1) * STAGE_B;
        const uint32_t aHiB = stage + 0 * TILE_B;
        const uint32_t aLoB = stage + 1 * TILE_B;
        const uint32_t wHiB = stage + 2 * TILE_B;
        const uint32_t wLoB = stage + 3 * TILE_B;

#pragma unroll
        for (int ks = 0; ks < 4; ks++) {
            const int kb = ks * 32 + khalf;

            uint32_t ah[2][4], al[2][4];
#pragma unroll
            for (int mt = 0; mt < 2; mt++) {
                int row = wm * 32 + mt * 16 + l15;
                uint32_t off = SW128(row * 128 + kb);
                LDSM_X4(ah[mt][0], ah[mt][1], ah[mt][2], ah[mt][3], aHiB + off);
                LDSM_X4(al[mt][0], al[mt][1], al[mt][2], al[mt][3], aLoB + off);
            }

            uint32_t bh[8][2], bl[8][2];
#pragma unroll
            for (int nq = 0; nq < 4; nq++) {       // each x4 covers 2 n-tiles
                int row = wn * 64 + nq * 16 + l15;
                uint32_t off = SW128(row * 128 + kb);
                uint32_t r0, r1, r2, r3;
                LDSM_X4(r0, r1, r2, r3, wHiB + off);
                bh[2 * nq][0] = r0; bh[2 * nq][1] = r2;
                bh[2 * nq + 1][0] = r1; bh[2 * nq + 1][1] = r3;
                LDSM_X4(r0, r1, r2, r3, wLoB + off);
                bl[2 * nq][0] = r0; bl[2 * nq][1] = r2;
                bl[2 * nq + 1][0] = r1; bl[2 * nq + 1][1] = r3;
            }

#pragma unroll
            for (int mt = 0; mt < 2; mt++)
#pragma unroll
                for (int nt = 0; nt < 8; nt++) {
                    MMA_BF16(acc[mt][nt], ah[mt], bh[nt]);
                    MMA_BF16(acc[mt][nt], ah[mt], bl[nt]);
                    MMA_BF16(acc[mt][nt], al[mt], bh[nt]);
                }
        }
        __syncthreads();
    }

    // ---- epilogue: fragments -> global ----
    const int groupID = lane >> 2;
    const int tg      = lane & 3;
#pragma unroll
    for (int mt = 0; mt < 2; mt++) {
#pragma unroll
        for (int half = 0; half < 2; half++) {
            int m = mBase + wm * 32 + mt * 16 + groupID + half * 8;
#pragma unroll
            for (int nt = 0; nt < 8; nt++) {
                int n = nBase + wn * 64 + nt * 8 + tg * 2;
                float2 v;
                v.x = acc[mt][nt][half * 2 + 0];
                v.y = acc[mt][nt][half * 2 + 1];
                if (!permute) {
                    *(float2*)&C[(size_t)m * DM + n] = v;
                } else {
                    int b = m >> 11;
                    int s = m & 2047;
                    int h = n >> 6;
                    int d = n & 63;
                    size_t addr = ((size_t)((b * HEADS + h) * S_LEN) + s) * DH + d;
                    *(float2*)&C[addr] = v;
                }
            }
        }
    }
}

// ---------------------------------------------------------------------------
// Flash attention (fp32, causal, online softmax) — unchanged (passing).
// ---------------------------------------------------------------------------
#define QSTR 68
__global__ __launch_bounds__(256) void flash_attn_kernel()
{
    extern __shared__ float sm[];
    float* Qt = sm;                     // [64][68]  Qt[d][q]
    float* KP = sm + 64 * QSTR;         // [64][68]  Kt[d][k]  then  Pt[k][q]
    float* Vs = sm + 2 * 64 * QSTR;     // [64][64]  Vs[k][d]

    const int tid = threadIdx.x;
    const int ty  = tid >> 4;
    const int tx  = tid & 15;

    const int bh = blockIdx.y;
    const int qt = blockIdx.x;

    const float* Qg = g_Q + (size_t)bh * S_LEN * DH + (size_t)qt * 64 * DH;
    const float* Kg = g_K + (size_t)bh * S_LEN * DH;
    const float* Vg = g_V + (size_t)bh * S_LEN * DH;

    for (int idx = tid; idx < 64 * 64; idx += 256) {
        int q = idx >> 6, d = idx & 63;
        Qt[d * QSTR + q] = Qg[(size_t)q * DH + d] * 0.125f;
    }

    float m_i[4], l_i[4], acc[4][4];
#pragma unroll
    for (int i = 0; i < 4; i++) {
        m_i[i] = -1e30f;
        l_i[i] = 0.0f;
#pragma unroll
        for (int j = 0; j < 4; j++) acc[i][j] = 0.0f;
    }

    for (int kt = 0; kt <= qt; ++kt) {
        const float* Kb = Kg + (size_t)kt * 64 * DH;
        const float* Vb = Vg + (size_t)kt * 64 * DH;

        for (int idx = tid; idx < 64 * 64; idx += 256) {
            int k = idx >> 6, d = idx & 63;
            KP[d * QSTR + k] = Kb[idx];
        }
        for (int idx = tid * 4; idx < 64 * 64; idx += 1024) {
            *reinterpret_cast<float4*>(&Vs[idx]) =
                *reinterpret_cast<const float4*>(&Vb[idx]);
        }
        __syncthreads();

        float s[4][4];
#pragma unroll
        for (int i = 0; i < 4; i++)
#pragma unroll
            for (int j = 0; j < 4; j++) s[i][j] = 0.0f;

#pragma unroll 8
        for (int d = 0; d < 64; d++) {
            float4 qa = *reinterpret_cast<const float4*>(&Qt[d * QSTR + ty * 4]);
            float4 kb = *reinterpret_cast<const float4*>(&KP[d * QSTR + tx * 4]);
            float qr[4] = {qa.x, qa.y, qa.z, qa.w};
            float kr[4] = {kb.x, kb.y, kb.z, kb.w};
#pragma unroll
            for (int i = 0; i < 4; i++)
#pragma unroll
                for (int j = 0; j < 4; j++)
                    s[i][j] = fmaf(qr[i], kr[j], s[i][j]);
        }

        if (kt == qt) {
#pragma unroll
            for (int i = 0; i < 4; i++)
#pragma unroll
                for (int j = 0; j < 4; j++)
                    if (tx * 4 + j > ty * 4 + i) s[i][j] = -1e30f;
        }

        float p[4][4];
#pragma unroll
        for (int i = 0; i < 4; i++) {
            float mx = fmaxf(fmaxf(s[i][0], s[i][1]), fmaxf(s[i][2], s[i][3]));
#pragma unroll
            for (int off = 8; off; off >>= 1)
                mx = fmaxf(mx, __shfl_xor_sync(0xffffffffu, mx, off, 16));
            float mnew = fmaxf(m_i[i], mx);
            float sc = __expf(m_i[i] - mnew);
            float ls = 0.0f;
#pragma unroll
            for (int j = 0; j < 4; j++) {
                p[i][j] = __expf(s[i][j] - mnew);
                ls += p[i][j];
            }
#pragma unroll
            for (int off = 8; off; off >>= 1)
                ls += __shfl_xor_sync(0xffffffffu, ls, off, 16);
            l_i[i] = l_i[i] * sc + ls;
#pragma unroll
            for (int j = 0; j < 4; j++) acc[i][j] *= sc;
            m_i[i] = mnew;
        }

        __syncthreads();

#pragma unroll
        for (int j = 0; j < 4; j++)
#pragma unroll
            for (int i = 0; i < 4; i++)
                KP[(tx * 4 + j) * QSTR + ty * 4 + i] = p[i][j];
        __syncthreads();

#pragma unroll 8
        for (int kk = 0; kk < 64; kk++) {
            float4 pa = *reinterpret_cast<const float4*>(&KP[kk * QSTR + ty * 4]);
            float4 vb = *reinterpret_cast<const float4*>(&Vs[kk * 64 + tx * 4]);
            float pr[4] = {pa.x, pa.y, pa.z, pa.w};
            float vr[4] = {vb.x, vb.y, vb.z, vb.w};
#pragma unroll
            for (int i = 0; i < 4; i++)
#pragma unroll
                for (int j = 0; j < 4; j++)
                    acc[i][j] = fmaf(pr[i], vr[j], acc[i][j]);
        }
        __syncthreads();
    }

    const int b = bh >> 4;
    const int h = bh & 15;
#pragma unroll
    for (int i = 0; i < 4; i++) {
        float rl = 1.0f / l_i[i];
        int sIdx = qt * 64 + ty * 4 + i;
        float4 v = make_float4(acc[i][0] * rl, acc[i][1] * rl,
                               acc[i][2] * rl, acc[i][3] * rl);
        size_t addr = (((size_t)(b * S_LEN + sIdx)) * HEADS + h) * DH + tx * 4;
        *reinterpret_cast<float4*>(&g_A[addr]) = v;
    }
}

// ---------------------------------------------------------------------------
// Launch
// ---------------------------------------------------------------------------
extern "C" void kernel_launch(void* const* d_in, const int* in_sizes, int n_in,
                              void* d_out, int out_size)
{
    const float* X  = (const float*)d_in[0];
    const float* WQ = (const float*)d_in[1];
    const float* WK = (const float*)d_in[2];
    const float* WV = (const float*)d_in[3];
    const float* WO = (const float*)d_in[4];
    float* out = (float*)d_out;

    float *Qp, *Kp, *Vp, *Ap;
    __nv_bfloat16 *Xhi, *Xlo, *Ahi, *Alo, *Whi, *Wlo;
    cudaGetSymbolAddress((void**)&Qp,  g_Q);
    cudaGetSymbolAddress((void**)&Kp,  g_K);
    cudaGetSymbolAddress((void**)&Vp,  g_V);
    cudaGetSymbolAddress((void**)&Ap,  g_A);
    cudaGetSymbolAddress((void**)&Xhi, g_Xhi);
    cudaGetSymbolAddress((void**)&Xlo, g_Xlo);
    cudaGetSymbolAddress((void**)&Ahi, g_Ahi);
    cudaGetSymbolAddress((void**)&Alo, g_Alo);
    cudaGetSymbolAddress((void**)&Whi, g_Whi);
    cudaGetSymbolAddress((void**)&Wlo, g_Wlo);

    const int smem_gemm = 2 * STAGE_B;   // 131072 B
    cudaFuncSetAttribute(tc_gemm,
                         cudaFuncAttributeMaxDynamicSharedMemorySize, smem_gemm);
    const int smem_flash = (2 * 64 * QSTR + 64 * 64) * sizeof(float);  // 51200 B
    cudaFuncSetAttribute(flash_attn_kernel,
                         cudaFuncAttributeMaxDynamicSharedMemorySize, smem_flash);

    const float* Ws[4] = {WQ, WK, WV, WO};

    // Splits
    split_kernel<<<4096, 256>>>((const float4*)X,
                                (__nv_bfloat162*)Xhi, (__nv_bfloat162*)Xlo,
                                MROWS * DM / 4);
    for (int w = 0; w < 4; w++)
        split_kernel<<<1024, 256>>>((const float4*)Ws[w],
                                    (__nv_bfloat162*)(Whi + (size_t)w * DM * DM),
                                    (__nv_bfloat162*)(Wlo + (size_t)w * DM * DM),
                                    DM * DM / 4);

    dim3 gGemm(DM / 128, MROWS / 128);   // (8, 64)

    tc_gemm<<<gGemm, 256, smem_gemm>>>(Xhi, Xlo, Whi + 0 * (size_t)DM * DM,
                                       Wlo + 0 * (size_t)DM * DM, Qp, 1);
    tc_gemm<<<gGemm, 256, smem_gemm>>>(Xhi, Xlo, Whi + 1 * (size_t)DM * DM,
                                       Wlo + 1 * (size_t)DM * DM, Kp, 1);
    tc_gemm<<<gGemm, 256, smem_gemm>>>(Xhi, Xlo, Whi + 2 * (size_t)DM * DM,
                                       Wlo + 2 * (size_t)DM * DM, Vp, 1);

    dim3 gFlash(S_LEN / 64, BATCH * HEADS);  // (32, 64)
    flash_attn_kernel<<<gFlash, 256, smem_flash>>>();

    split_kernel<<<4096, 256>>>((const float4*)Ap,
                                (__nv_bfloat162*)Ahi, (__nv_bfloat162*)Alo,
                                MROWS * DM / 4);
    tc_gemm<<<gGemm, 256, smem_gemm>>>(Ahi, Alo, Whi + 3 * (size_t)DM * DM,
                                       Wlo + 3 * (size_t)DM * DM, out, 0);
}

// round 4
// speedup vs baseline: 2.8522x; 1.7561x over previous
#include <cuda_runtime.h>
#include <cuda_bf16.h>
#include <cstdint>

// Problem constants
#define BATCH 4
#define S_LEN 2048
#define HEADS 16
#define DH    64
#define DM    1024
#define MROWS (BATCH * S_LEN)   // 8192
#define HS    (BATCH * HEADS * S_LEN * DH)   // 8388608

// ---------------------------------------------------------------------------
// Device scratch (no allocation allowed)
// ---------------------------------------------------------------------------
__device__ __nv_bfloat16 g_Xhi[MROWS * DM];
__device__ __nv_bfloat16 g_Xlo[MROWS * DM];
__device__ __nv_bfloat16 g_Whi[4][DM * DM];
__device__ __nv_bfloat16 g_Wlo[4][DM * DM];
__device__ __nv_bfloat16 g_Qhi[HS], g_Qlo[HS];   // [B,H,S,Dh]
__device__ __nv_bfloat16 g_Khi[HS], g_Klo[HS];
__device__ __nv_bfloat16 g_Vhi[HS], g_Vlo[HS];
__device__ __nv_bfloat16 g_Ahi[MROWS * DM];      // attn out [B,S,H*Dh]
__device__ __nv_bfloat16 g_Alo[MROWS * DM];

// ---------------------------------------------------------------------------
// PTX helpers
// ---------------------------------------------------------------------------
__device__ __forceinline__ uint32_t smem_to_u32(const void* p) {
    uint32_t a;
    asm("{ .reg .u64 t; cvta.to.shared.u64 t, %1; cvt.u32.u64 %0, t; }"
        : "=r"(a) : "l"(p));
    return a;
}

#define CP_ASYNC16(smem_u32, gptr) \
    asm volatile("cp.async.cg.shared.global [%0], [%1], 16;" \
                 :: "r"(smem_u32), "l"(__cvta_generic_to_global(gptr)) : "memory")
#define CP_COMMIT()  asm volatile("cp.async.commit_group;" ::: "memory")

#define LDSM_X4(r0, r1, r2, r3, addr) \
    asm volatile("ldmatrix.sync.aligned.m8n8.x4.shared.b16 {%0,%1,%2,%3}, [%4];" \
                 : "=r"(r0), "=r"(r1), "=r"(r2), "=r"(r3) : "r"(addr))

#define LDSM_X4_T(r0, r1, r2, r3, addr) \
    asm volatile("ldmatrix.sync.aligned.m8n8.x4.trans.shared.b16 {%0,%1,%2,%3}, [%4];" \
                 : "=r"(r0), "=r"(r1), "=r"(r2), "=r"(r3) : "r"(addr))

#define MMA_BF16(d, a, b) \
    asm volatile("mma.sync.aligned.m16n8k16.row.col.f32.bf16.bf16.f32 " \
                 "{%0,%1,%2,%3}, {%4,%5,%6,%7}, {%8,%9}, {%0,%1,%2,%3};" \
                 : "+f"((d)[0]), "+f"((d)[1]), "+f"((d)[2]), "+f"((d)[3]) \
                 : "r"((a)[0]), "r"((a)[1]), "r"((a)[2]), "r"((a)[3]), \
                   "r"((b)[0]), "r"((b)[1]))

#define SW128(off) ((off) ^ (((off) >> 3) & 0x70))

__device__ __forceinline__ float ex2f(float x) {
    float r;
    asm("ex2.approx.ftz.f32 %0, %1;" : "=f"(r) : "f"(x));
    return r;
}

// (f0, f1) -> bf16x2 hi word + bf16x2 lo word (residual)
__device__ __forceinline__ void split2(float f0, float f1, uint32_t& hi, uint32_t& lo) {
    __nv_bfloat16 h0 = __float2bfloat16(f0), h1 = __float2bfloat16(f1);
    __nv_bfloat162 hv; hv.x = h0; hv.y = h1;
    hi = *(uint32_t*)&hv;
    float r0 = f0 - __bfloat162float(h0);
    float r1 = f1 - __bfloat162float(h1);
    __nv_bfloat16 l0 = __float2bfloat16(r0), l1 = __float2bfloat16(r1);
    __nv_bfloat162 lv; lv.x = l0; lv.y = l1;
    lo = *(uint32_t*)&lv;
}

// ---------------------------------------------------------------------------
// fp32 -> (hi, lo) bf16 split (inputs X and W only)
// ---------------------------------------------------------------------------
__global__ __launch_bounds__(256) void split_kernel(const float4* __restrict__ x,
                                                    __nv_bfloat162* __restrict__ hi2,
                                                    __nv_bfloat162* __restrict__ lo2,
                                                    int n4)
{
    for (int i = blockIdx.x * blockDim.x + threadIdx.x; i < n4;
         i += gridDim.x * blockDim.x) {
        float4 v = x[i];
        uint32_t h0, l0, h1, l1;
        split2(v.x, v.y, h0, l0);
        split2(v.z, v.w, h1, l1);
        ((uint32_t*)hi2)[2 * i]     = h0;
        ((uint32_t*)hi2)[2 * i + 1] = h1;
        ((uint32_t*)lo2)[2 * i]     = l0;
        ((uint32_t*)lo2)[2 * i + 1] = l1;
    }
}

// ---------------------------------------------------------------------------
// HMMA GEMM:  C[M=8192, N=1024] = A[M,K=1024] @ W[N,K]^T  (split-bf16, 3 products)
// mode 0: fp32 C row-major.  mode 1: bf16 hi/lo outputs, scattered to [B,H,S,Dh].
// ---------------------------------------------------------------------------
#define TILE_B   16384
#define STAGE_B  (4 * TILE_B)

__global__ __launch_bounds__(256) void tc_gemm(const __nv_bfloat16* __restrict__ Ahi,
                                               const __nv_bfloat16* __restrict__ Alo,
                                               const __nv_bfloat16* __restrict__ Whi,
                                               const __nv_bfloat16* __restrict__ Wlo,
                                               float* __restrict__ Cf,
                                               __nv_bfloat16* __restrict__ Chi,
                                               __nv_bfloat16* __restrict__ Clo,
                                               int mode)
{
    extern __shared__ __align__(1024) char smem[];
    const uint32_t sb = smem_to_u32(smem);
    const int tid  = threadIdx.x;
    const int wid  = tid >> 5;
    const int lane = tid & 31;

    const int mBase = blockIdx.y * 128;
    const int nBase = blockIdx.x * 128;

    const int wm = wid & 3;
    const int wn = wid >> 2;

    const char* srcs[4] = {
        (const char*)(Ahi + (size_t)mBase * DM),
        (const char*)(Alo + (size_t)mBase * DM),
        (const char*)(Whi + (size_t)nBase * DM),
        (const char*)(Wlo + (size_t)nBase * DM)
    };

    const int l15   = lane & 15;
    const int khalf = ((lane >> 4) & 1) * 16;

    float acc[2][8][4];
#pragma unroll
    for (int mt = 0; mt < 2; mt++)
#pragma unroll
        for (int nt = 0; nt < 8; nt++)
#pragma unroll
            for (int r = 0; r < 4; r++) acc[mt][nt][r] = 0.0f;

    auto load_stage = [&](int ic, int buf) {
        const uint32_t stage = sb + buf * STAGE_B;
#pragma unroll
        for (int t = 0; t < 4; t++) {
            const char* src = srcs[t];
#pragma unroll
            for (int r = 0; r < 4; r++) {
                int unit = r * 256 + tid;
                int row  = unit >> 3;
                int c16  = unit & 7;
                const char* g = src + (size_t)row * (DM * 2) + ic * 128 + c16 * 16;
                uint32_t so = stage + t * TILE_B + SW128(row * 128 + c16 * 16);
                CP_ASYNC16(so, g);
            }
        }
        CP_COMMIT();
    };

    load_stage(0, 0);

    for (int ic = 0; ic < 16; ic++) {
        if (ic < 15) load_stage(ic + 1, (ic + 1) & 1);
        if (ic < 15) asm volatile("cp.async.wait_group 1;" ::: "memory");
        else         asm volatile("cp.async.wait_group 0;" ::: "memory");
        __syncthreads();

        const uint32_t stage = sb + (ic & 1) * STAGE_B;
        const uint32_t aHiB = stage + 0 * TILE_B;
        const uint32_t aLoB = stage + 1 * TILE_B;
        const uint32_t wHiB = stage + 2 * TILE_B;
        const uint32_t wLoB = stage + 3 * TILE_B;

#pragma unroll
        for (int ks = 0; ks < 4; ks++) {
            const int kb = ks * 32 + khalf;

            uint32_t ah[2][4], al[2][4];
#pragma unroll
            for (int mt = 0; mt < 2; mt++) {
                int row = wm * 32 + mt * 16 + l15;
                uint32_t off = SW128(row * 128 + kb);
                LDSM_X4(ah[mt][0], ah[mt][1], ah[mt][2], ah[mt][3], aHiB + off);
                LDSM_X4(al[mt][0], al[mt][1], al[mt][2], al[mt][3], aLoB + off);
            }

            uint32_t bh[8][2], bl[8][2];
#pragma unroll
            for (int nq = 0; nq < 4; nq++) {
                int row = wn * 64 + nq * 16 + l15;
                uint32_t off = SW128(row * 128 + kb);
                uint32_t r0, r1, r2, r3;
                LDSM_X4(r0, r1, r2, r3, wHiB + off);
                bh[2 * nq][0] = r0; bh[2 * nq][1] = r2;
                bh[2 * nq + 1][0] = r1; bh[2 * nq + 1][1] = r3;
                LDSM_X4(r0, r1, r2, r3, wLoB + off);
                bl[2 * nq][0] = r0; bl[2 * nq][1] = r2;
                bl[2 * nq + 1][0] = r1; bl[2 * nq + 1][1] = r3;
            }

#pragma unroll
            for (int mt = 0; mt < 2; mt++)
#pragma unroll
                for (int nt = 0; nt < 8; nt++) {
                    MMA_BF16(acc[mt][nt], ah[mt], bh[nt]);
                    MMA_BF16(acc[mt][nt], ah[mt], bl[nt]);
                    MMA_BF16(acc[mt][nt], al[mt], bh[nt]);
                }
        }
        __syncthreads();
    }

    // epilogue
    const int groupID = lane >> 2;
    const int tg      = lane & 3;
#pragma unroll
    for (int mt = 0; mt < 2; mt++) {
#pragma unroll
        for (int half = 0; half < 2; half++) {
            int m = mBase + wm * 32 + mt * 16 + groupID + half * 8;
#pragma unroll
            for (int nt = 0; nt < 8; nt++) {
                int n = nBase + wn * 64 + nt * 8 + tg * 2;
                float f0 = acc[mt][nt][half * 2 + 0];
                float f1 = acc[mt][nt][half * 2 + 1];
                if (mode == 0) {
                    float2 v; v.x = f0; v.y = f1;
                    *(float2*)&Cf[(size_t)m * DM + n] = v;
                } else {
                    int b = m >> 11;
                    int s = m & 2047;
                    int h = n >> 6;
                    int d = n & 63;
                    size_t addr = ((size_t)((b * HEADS + h) * S_LEN) + s) * DH + d;
                    uint32_t hi, lo;
                    split2(f0, f1, hi, lo);
                    *(uint32_t*)&Chi[addr] = hi;
                    *(uint32_t*)&Clo[addr] = lo;
                }
            }
        }
    }
}

// ---------------------------------------------------------------------------
// HMMA flash attention (causal, online softmax, split-bf16 both matmuls).
// Block: 256 threads (8 warps), 128 q-rows (warp wid owns rows wid*16..+15).
// kt loop over 64-row K/V tiles, cp.async double-buffered.
// SMEM: Qhi 16K | Qlo 16K | 2 stages x (Khi 8K | Klo 8K | Vhi 8K | Vlo 8K).
// ---------------------------------------------------------------------------
#define FS_STAGE 32768
#define FS_TOTAL (FS_STAGE + 2 * 32768)   // 98304

__global__ __launch_bounds__(256) void flash_mma_kernel()
{
    extern __shared__ __align__(1024) char smem[];
    const uint32_t sb = smem_to_u32(smem);
    const int tid  = threadIdx.x;
    const int wid  = tid >> 5;
    const int lane = tid & 31;
    const int g    = lane >> 2;      // groupID
    const int tg   = lane & 3;
    const int l15  = lane & 15;
    const int khalf = ((lane >> 4) & 1) * 16;

    const int qt = (gridDim.x - 1) - blockIdx.x;   // heavy blocks first
    const int bh = blockIdx.y;
    const int qtBase = qt * 128;
    const int ktmax  = qt * 2 + 1;

    const size_t headBase = (size_t)bh * S_LEN * DH;

    const __nv_bfloat16* kvsrc[4] = {
        g_Khi + headBase, g_Klo + headBase, g_Vhi + headBase, g_Vlo + headBase
    };

    // ---- load Q (hi, lo) once ----
    {
        const __nv_bfloat16* qsrc[2] = { g_Qhi + headBase + (size_t)qtBase * DH,
                                         g_Qlo + headBase + (size_t)qtBase * DH };
#pragma unroll
        for (int t = 0; t < 2; t++) {
#pragma unroll
            for (int r = 0; r < 4; r++) {
                int unit = r * 256 + tid;     // 0..1023
                int row  = unit >> 3;         // 0..127
                int c16  = unit & 7;
                const char* gp = (const char*)(qsrc[t] + (size_t)row * DH) + c16 * 16;
                uint32_t so = sb + t * 16384 + SW128(row * 128 + c16 * 16);
                CP_ASYNC16(so, gp);
            }
        }
        CP_COMMIT();
    }

    auto load_kv = [&](int kt, int buf) {
        const uint32_t st = sb + FS_STAGE + buf * 32768;
        const size_t kvoff = (size_t)kt * 64 * DH;
#pragma unroll
        for (int t = 0; t < 4; t++) {
            const __nv_bfloat16* base = kvsrc[t] + kvoff;
#pragma unroll
            for (int r = 0; r < 2; r++) {
                int unit = r * 256 + tid;     // 0..511
                int row  = unit >> 3;         // 0..63
                int c16  = unit & 7;
                const char* gp = (const char*)(base + (size_t)row * DH) + c16 * 16;
                uint32_t so = st + t * 8192 + SW128(row * 128 + c16 * 16);
                CP_ASYNC16(so, gp);
            }
        }
        CP_COMMIT();
    };

    load_kv(0, 0);

    uint32_t qhi[4][4], qlo[4][4];
    float o[8][4];
    float m_i[2] = { -1e30f, -1e30f };
    float l_i[2] = { 0.0f, 0.0f };
#pragma unroll
    for (int dt = 0; dt < 8; dt++)
#pragma unroll
        for (int r = 0; r < 4; r++) o[dt][r] = 0.0f;

    const float C1 = 0.18033688011112042f;    // log2(e) / sqrt(64)

    for (int kt = 0; kt <= ktmax; kt++) {
        if (kt < ktmax) load_kv(kt + 1, (kt + 1) & 1);
        if (kt < ktmax) asm volatile("cp.async.wait_group 1;" ::: "memory");
        else            asm volatile("cp.async.wait_group 0;" ::: "memory");
        __syncthreads();

        if (kt == 0) {
            // Q fragments (once)
#pragma unroll
            for (int ks = 0; ks < 4; ks++) {
                int row = wid * 16 + l15;
                uint32_t off = SW128(row * 128 + ks * 32 + khalf);
                LDSM_X4(qhi[ks][0], qhi[ks][1], qhi[ks][2], qhi[ks][3], sb + off);
                LDSM_X4(qlo[ks][0], qlo[ks][1], qlo[ks][2], qlo[ks][3], sb + 16384 + off);
            }
        }

        const uint32_t st   = sb + FS_STAGE + (kt & 1) * 32768;
        const uint32_t KhiB = st;
        const uint32_t KloB = st + 8192;
        const uint32_t VhiB = st + 16384;
        const uint32_t VloB = st + 24576;

        // ---- S = Q K^T (split, 3 products) ----
        float sacc[8][4];
#pragma unroll
        for (int nt = 0; nt < 8; nt++)
#pragma unroll
            for (int r = 0; r < 4; r++) sacc[nt][r] = 0.0f;

#pragma unroll
        for (int ks = 0; ks < 4; ks++) {
            const int kb = ks * 32 + khalf;
            uint32_t kh[8][2], kl[8][2];
#pragma unroll
            for (int nq = 0; nq < 4; nq++) {
                int row = nq * 16 + l15;
                uint32_t off = SW128(row * 128 + kb);
                uint32_t r0, r1, r2, r3;
                LDSM_X4(r0, r1, r2, r3, KhiB + off);
                kh[2 * nq][0] = r0; kh[2 * nq][1] = r2;
                kh[2 * nq + 1][0] = r1; kh[2 * nq + 1][1] = r3;
                LDSM_X4(r0, r1, r2, r3, KloB + off);
                kl[2 * nq][0] = r0; kl[2 * nq][1] = r2;
                kl[2 * nq + 1][0] = r1; kl[2 * nq + 1][1] = r3;
            }
#pragma unroll
            for (int nt = 0; nt < 8; nt++) {
                MMA_BF16(sacc[nt], qhi[ks], kh[nt]);
                MMA_BF16(sacc[nt], qhi[ks], kl[nt]);
                MMA_BF16(sacc[nt], qlo[ks], kh[nt]);
            }
        }

        // ---- causal mask (only tiles straddling the diagonal) ----
        if (kt >= 2 * qt) {
            const int q0 = qtBase + wid * 16 + g;
            const int kcb = kt * 64;
#pragma unroll
            for (int nt = 0; nt < 8; nt++) {
                int kc = kcb + nt * 8 + tg * 2;
                if (kc     > q0)     sacc[nt][0] = -1e30f;
                if (kc + 1 > q0)     sacc[nt][1] = -1e30f;
                if (kc     > q0 + 8) sacc[nt][2] = -1e30f;
                if (kc + 1 > q0 + 8) sacc[nt][3] = -1e30f;
            }
        }

        // ---- online softmax (rows i=0 -> c0,c1 ; i=1 -> c2,c3) ----
#pragma unroll
        for (int i = 0; i < 2; i++) {
            float mx = -1e30f;
#pragma unroll
            for (int nt = 0; nt < 8; nt++) {
                mx = fmaxf(mx, sacc[nt][2 * i]);
                mx = fmaxf(mx, sacc[nt][2 * i + 1]);
            }
            mx = fmaxf(mx, __shfl_xor_sync(0xffffffffu, mx, 1));
            mx = fmaxf(mx, __shfl_xor_sync(0xffffffffu, mx, 2));
            float mnew = fmaxf(m_i[i], mx);
            float corr = ex2f((m_i[i] - mnew) * C1);
            m_i[i] = mnew;
            float sum = 0.0f;
#pragma unroll
            for (int nt = 0; nt < 8; nt++) {
#pragma unroll
                for (int j = 0; j < 2; j++) {
                    float p = ex2f((sacc[nt][2 * i + j] - mnew) * C1);
                    sacc[nt][2 * i + j] = p;
                    sum += p;
                }
            }
            sum += __shfl_xor_sync(0xffffffffu, sum, 1);
            sum += __shfl_xor_sync(0xffffffffu, sum, 2);
            l_i[i] = l_i[i] * corr + sum;
#pragma unroll
            for (int dt = 0; dt < 8; dt++) {
                o[dt][2 * i]     *= corr;
                o[dt][2 * i + 1] *= corr;
            }
        }

        // ---- P fragments (split hi/lo) ----
        uint32_t phi[4][4], plo[4][4];
#pragma unroll
        for (int ks = 0; ks < 4; ks++) {
            split2(sacc[2 * ks][0],     sacc[2 * ks][1],     phi[ks][0], plo[ks][0]);
            split2(sacc[2 * ks][2],     sacc[2 * ks][3],     phi[ks][1], plo[ks][1]);
            split2(sacc[2 * ks + 1][0], sacc[2 * ks + 1][1], phi[ks][2], plo[ks][2]);
            split2(sacc[2 * ks + 1][2], sacc[2 * ks + 1][3], phi[ks][3], plo[ks][3]);
        }

        // ---- O += P V (split, 3 products) ----
#pragma unroll
        for (int ks = 0; ks < 4; ks++) {
            uint32_t vh[8][2], vl[8][2];
#pragma unroll
            for (int dp = 0; dp < 4; dp++) {
                uint32_t off = SW128((ks * 16 + l15) * 128 + dp * 32 + khalf);
                uint32_t r0, r1, r2, r3;
                LDSM_X4_T(r0, r1, r2, r3, VhiB + off);
                vh[2 * dp][0] = r0; vh[2 * dp][1] = r1;
                vh[2 * dp + 1][0] = r2; vh[2 * dp + 1][1] = r3;
                LDSM_X4_T(r0, r1, r2, r3, VloB + off);
                vl[2 * dp][0] = r0; vl[2 * dp][1] = r1;
                vl[2 * dp + 1][0] = r2; vl[2 * dp + 1][1] = r3;
            }
#pragma unroll
            for (int dt = 0; dt < 8; dt++) {
                MMA_BF16(o[dt], phi[ks], vh[dt]);
                MMA_BF16(o[dt], phi[ks], vl[dt]);
                MMA_BF16(o[dt], plo[ks], vh[dt]);
            }
        }

        __syncthreads();
    }

    // ---- epilogue: O/l -> bf16 hi/lo into [B,S,DM] ----
    const int b = bh >> 4;
    const int h = bh & 15;
#pragma unroll
    for (int i = 0; i < 2; i++) {
        float inv = 1.0f / l_i[i];
        int srow = qtBase + wid * 16 + g + 8 * i;
        size_t rowaddr = ((size_t)(b * S_LEN + srow)) * DM + h * 64;
#pragma unroll
        for (int dt = 0; dt < 8; dt++) {
            float f0 = o[dt][2 * i]     * inv;
            float f1 = o[dt][2 * i + 1] * inv;
            uint32_t hi, lo;
            split2(f0, f1, hi, lo);
            size_t addr = rowaddr + dt * 8 + tg * 2;
            *(uint32_t*)&g_Ahi[addr] = hi;
            *(uint32_t*)&g_Alo[addr] = lo;
        }
    }
}

// ---------------------------------------------------------------------------
// Launch
// ---------------------------------------------------------------------------
extern "C" void kernel_launch(void* const* d_in, const int* in_sizes, int n_in,
                              void* d_out, int out_size)
{
    const float* X  = (const float*)d_in[0];
    const float* WQ = (const float*)d_in[1];
    const float* WK = (const float*)d_in[2];
    const float* WV = (const float*)d_in[3];
    const float* WO = (const float*)d_in[4];
    float* out = (float*)d_out;

    __nv_bfloat16 *Xhi, *Xlo, *Whi, *Wlo;
    __nv_bfloat16 *Qhi, *Qlo, *Khi, *Klo, *Vhi, *Vlo, *Ahi, *Alo;
    cudaGetSymbolAddress((void**)&Xhi, g_Xhi);
    cudaGetSymbolAddress((void**)&Xlo, g_Xlo);
    cudaGetSymbolAddress((void**)&Whi, g_Whi);
    cudaGetSymbolAddress((void**)&Wlo, g_Wlo);
    cudaGetSymbolAddress((void**)&Qhi, g_Qhi);
    cudaGetSymbolAddress((void**)&Qlo, g_Qlo);
    cudaGetSymbolAddress((void**)&Khi, g_Khi);
    cudaGetSymbolAddress((void**)&Klo, g_Klo);
    cudaGetSymbolAddress((void**)&Vhi, g_Vhi);
    cudaGetSymbolAddress((void**)&Vlo, g_Vlo);
    cudaGetSymbolAddress((void**)&Ahi, g_Ahi);
    cudaGetSymbolAddress((void**)&Alo, g_Alo);

    const int smem_gemm = 2 * STAGE_B;   // 131072
    cudaFuncSetAttribute(tc_gemm,
                         cudaFuncAttributeMaxDynamicSharedMemorySize, smem_gemm);
    cudaFuncSetAttribute(flash_mma_kernel,
                         cudaFuncAttributeMaxDynamicSharedMemorySize, FS_TOTAL);

    const float* Ws[4] = {WQ, WK, WV, WO};

    split_kernel<<<4096, 256>>>((const float4*)X,
                                (__nv_bfloat162*)Xhi, (__nv_bfloat162*)Xlo,
                                MROWS * DM / 4);
    for (int w = 0; w < 4; w++)
        split_kernel<<<1024, 256>>>((const float4*)Ws[w],
                                    (__nv_bfloat162*)(Whi + (size_t)w * DM * DM),
                                    (__nv_bfloat162*)(Wlo + (size_t)w * DM * DM),
                                    DM * DM / 4);

    dim3 gGemm(DM / 128, MROWS / 128);   // (8, 64)

    tc_gemm<<<gGemm, 256, smem_gemm>>>(Xhi, Xlo, Whi + 0 * (size_t)DM * DM,
                                       Wlo + 0 * (size_t)DM * DM,
                                       nullptr, Qhi, Qlo, 1);
    tc_gemm<<<gGemm, 256, smem_gemm>>>(Xhi, Xlo, Whi + 1 * (size_t)DM * DM,
                                       Wlo + 1 * (size_t)DM * DM,
                                       nullptr, Khi, Klo, 1);
    tc_gemm<<<gGemm, 256, smem_gemm>>>(Xhi, Xlo, Whi + 2 * (size_t)DM * DM,
                                       Wlo + 2 * (size_t)DM * DM,
                                       nullptr, Vhi, Vlo, 1);

    dim3 gFlash(S_LEN / 128, BATCH * HEADS);  // (16, 64)
    flash_mma_kernel<<<gFlash, 256, FS_TOTAL>>>();

    tc_gemm<<<gGemm, 256, smem_gemm>>>(Ahi, Alo, Whi + 3 * (size_t)DM * DM,
                                       Wlo + 3 * (size_t)DM * DM,
                                       out, nullptr, nullptr, 0);
}

// round 5
// speedup vs baseline: 4.4191x; 1.5493x over previous
#include <cuda_runtime.h>
#include <cuda_fp16.h>
#include <cstdint>

// Problem constants
#define BATCH 4
#define S_LEN 2048
#define HEADS 16
#define DH    64
#define DM    1024
#define MROWS (BATCH * S_LEN)   // 8192
#define HS    (BATCH * HEADS * S_LEN * DH)   // 8388608

// ---------------------------------------------------------------------------
// Device scratch (fp16). A-side operands keep hi+lo; B-side operands hi only.
// ---------------------------------------------------------------------------
__device__ __half g_Xhi[MROWS * DM];
__device__ __half g_Xlo[MROWS * DM];
__device__ __half g_Wh[4][DM * DM];          // weights: hi only (B-side)
__device__ __half g_Qhi[HS], g_Qlo[HS];      // [B,H,S,Dh]  (A-side in QK)
__device__ __half g_Kh[HS];                  // B-side in QK
__device__ __half g_Vh[HS];                  // B-side in PV
__device__ __half g_Ahi[MROWS * DM];         // attn out [B,S,H*Dh] (A-side)
__device__ __half g_Alo[MROWS * DM];

// ---------------------------------------------------------------------------
// PTX helpers
// ---------------------------------------------------------------------------
__device__ __forceinline__ uint32_t smem_to_u32(const void* p) {
    uint32_t a;
    asm("{ .reg .u64 t; cvta.to.shared.u64 t, %1; cvt.u32.u64 %0, t; }"
        : "=r"(a) : "l"(p));
    return a;
}

#define CP_ASYNC16(smem_u32, gptr) \
    asm volatile("cp.async.cg.shared.global [%0], [%1], 16;" \
                 :: "r"(smem_u32), "l"(__cvta_generic_to_global(gptr)) : "memory")
#define CP_COMMIT()  asm volatile("cp.async.commit_group;" ::: "memory")

#define LDSM_X4(r0, r1, r2, r3, addr) \
    asm volatile("ldmatrix.sync.aligned.m8n8.x4.shared.b16 {%0,%1,%2,%3}, [%4];" \
                 : "=r"(r0), "=r"(r1), "=r"(r2), "=r"(r3) : "r"(addr))

#define LDSM_X4_T(r0, r1, r2, r3, addr) \
    asm volatile("ldmatrix.sync.aligned.m8n8.x4.trans.shared.b16 {%0,%1,%2,%3}, [%4];" \
                 : "=r"(r0), "=r"(r1), "=r"(r2), "=r"(r3) : "r"(addr))

#define MMA_F16(d, a, b) \
    asm volatile("mma.sync.aligned.m16n8k16.row.col.f32.f16.f16.f32 " \
                 "{%0,%1,%2,%3}, {%4,%5,%6,%7}, {%8,%9}, {%0,%1,%2,%3};" \
                 : "+f"((d)[0]), "+f"((d)[1]), "+f"((d)[2]), "+f"((d)[3]) \
                 : "r"((a)[0]), "r"((a)[1]), "r"((a)[2]), "r"((a)[3]), \
                   "r"((b)[0]), "r"((b)[1]))

#define SW128(off) ((off) ^ (((off) >> 3) & 0x70))

__device__ __forceinline__ float ex2f(float x) {
    float r;
    asm("ex2.approx.ftz.f32 %0, %1;" : "=f"(r) : "f"(x));
    return r;
}

__device__ __forceinline__ uint32_t pack_h2(float a, float b) {
    __half2 h = __floats2half2_rn(a, b);
    return *(uint32_t*)&h;
}

// (f0,f1) -> fp16x2 hi word + fp16x2 lo word (residual)
__device__ __forceinline__ void split2h(float f0, float f1, uint32_t& hi, uint32_t& lo) {
    __half h0 = __float2half_rn(f0), h1 = __float2half_rn(f1);
    __half2 hv = __halves2half2(h0, h1);
    hi = *(uint32_t*)&hv;
    float r0 = f0 - __half2float(h0);
    float r1 = f1 - __half2float(h1);
    __half2 lv = __floats2half2_rn(r0, r1);
    lo = *(uint32_t*)&lv;
}

// ---------------------------------------------------------------------------
// Input conversion kernels
// ---------------------------------------------------------------------------
__global__ __launch_bounds__(256) void splitX_kernel(const float4* __restrict__ x, int n4)
{
    uint32_t* hi = (uint32_t*)g_Xhi;
    uint32_t* lo = (uint32_t*)g_Xlo;
    for (int i = blockIdx.x * blockDim.x + threadIdx.x; i < n4;
         i += gridDim.x * blockDim.x) {
        float4 v = x[i];
        uint32_t h0, l0, h1, l1;
        split2h(v.x, v.y, h0, l0);
        split2h(v.z, v.w, h1, l1);
        hi[2 * i] = h0; hi[2 * i + 1] = h1;
        lo[2 * i] = l0; lo[2 * i + 1] = l1;
    }
}

__global__ __launch_bounds__(256) void convW_kernel(const float4* __restrict__ w0,
                                                    const float4* __restrict__ w1,
                                                    const float4* __restrict__ w2,
                                                    const float4* __restrict__ w3,
                                                    int n4)
{
    const int z = blockIdx.z;
    const float4* src = (z == 0) ? w0 : (z == 1) ? w1 : (z == 2) ? w2 : w3;
    uint32_t* dst = (uint32_t*)g_Wh[z];
    for (int i = blockIdx.x * blockDim.x + threadIdx.x; i < n4;
         i += gridDim.x * blockDim.x) {
        float4 v = src[i];
        dst[2 * i]     = pack_h2(v.x, v.y);
        dst[2 * i + 1] = pack_h2(v.z, v.w);
    }
}

// ---------------------------------------------------------------------------
// fp16 2-product HMMA GEMM body:
//   C[128x128 tile] of A[M,K=1024] @ W[N,K]^T,  D = Ahi*Wh + Alo*Wh
// Tile 128x128, K-chunk 64 (128B rows, SW128), cp.async double-buffered.
// Stage: Ahi 16K | Alo 16K | Wh 16K = 48KB; 2 stages = 96KB.
// mode 0: fp32 row-major. mode 1: hi+lo fp16 scatter [B,H,S,Dh].
// mode 2: hi fp16 scatter only.
// ---------------------------------------------------------------------------
#define TILE_B   16384
#define STAGE_B  (3 * TILE_B)

__device__ __forceinline__ void gemm_body(const __half* __restrict__ Ahi,
                                          const __half* __restrict__ Alo,
                                          const __half* __restrict__ Wh,
                                          float* __restrict__ Cf,
                                          __half* __restrict__ Chi,
                                          __half* __restrict__ Clo,
                                          int mode, int mBase, int nBase,
                                          uint32_t sb)
{
    const int tid  = threadIdx.x;
    const int wid  = tid >> 5;
    const int lane = tid & 31;
    const int wm = wid & 3;
    const int wn = wid >> 2;
    const int l15   = lane & 15;
    const int khalf = ((lane >> 4) & 1) * 16;

    const char* srcs[3] = {
        (const char*)(Ahi + (size_t)mBase * DM),
        (const char*)(Alo + (size_t)mBase * DM),
        (const char*)(Wh  + (size_t)nBase * DM)
    };

    float acc[2][8][4];
#pragma unroll
    for (int mt = 0; mt < 2; mt++)
#pragma unroll
        for (int nt = 0; nt < 8; nt++)
#pragma unroll
            for (int r = 0; r < 4; r++) acc[mt][nt][r] = 0.0f;

    auto load_stage = [&](int ic, int buf) {
        const uint32_t stage = sb + buf * STAGE_B;
#pragma unroll
        for (int t = 0; t < 3; t++) {
            const char* src = srcs[t];
#pragma unroll
            for (int r = 0; r < 4; r++) {
                int unit = r * 256 + tid;
                int row  = unit >> 3;
                int c16  = unit & 7;
                const char* g = src + (size_t)row * (DM * 2) + ic * 128 + c16 * 16;
                uint32_t so = stage + t * TILE_B + SW128(row * 128 + c16 * 16);
                CP_ASYNC16(so, g);
            }
        }
        CP_COMMIT();
    };

    load_stage(0, 0);

    for (int ic = 0; ic < 16; ic++) {
        if (ic < 15) load_stage(ic + 1, (ic + 1) & 1);
        if (ic < 15) asm volatile("cp.async.wait_group 1;" ::: "memory");
        else         asm volatile("cp.async.wait_group 0;" ::: "memory");
        __syncthreads();

        const uint32_t stage = sb + (ic & 1) * STAGE_B;
        const uint32_t aHiB = stage + 0 * TILE_B;
        const uint32_t aLoB = stage + 1 * TILE_B;
        const uint32_t wB   = stage + 2 * TILE_B;

#pragma unroll
        for (int ks = 0; ks < 4; ks++) {
            const int kb = ks * 32 + khalf;

            uint32_t ah[2][4], al[2][4];
#pragma unroll
            for (int mt = 0; mt < 2; mt++) {
                int row = wm * 32 + mt * 16 + l15;
                uint32_t off = SW128(row * 128 + kb);
                LDSM_X4(ah[mt][0], ah[mt][1], ah[mt][2], ah[mt][3], aHiB + off);
                LDSM_X4(al[mt][0], al[mt][1], al[mt][2], al[mt][3], aLoB + off);
            }

            uint32_t bh[8][2];
#pragma unroll
            for (int nq = 0; nq < 4; nq++) {
                int row = wn * 64 + nq * 16 + l15;
                uint32_t off = SW128(row * 128 + kb);
                uint32_t r0, r1, r2, r3;
                LDSM_X4(r0, r1, r2, r3, wB + off);
                bh[2 * nq][0] = r0; bh[2 * nq][1] = r2;
                bh[2 * nq + 1][0] = r1; bh[2 * nq + 1][1] = r3;
            }

#pragma unroll
            for (int mt = 0; mt < 2; mt++)
#pragma unroll
                for (int nt = 0; nt < 8; nt++) {
                    MMA_F16(acc[mt][nt], ah[mt], bh[nt]);
                    MMA_F16(acc[mt][nt], al[mt], bh[nt]);
                }
        }
        __syncthreads();
    }

    // epilogue
    const int groupID = lane >> 2;
    const int tg      = lane & 3;
#pragma unroll
    for (int mt = 0; mt < 2; mt++) {
#pragma unroll
        for (int half = 0; half < 2; half++) {
            int m = mBase + wm * 32 + mt * 16 + groupID + half * 8;
#pragma unroll
            for (int nt = 0; nt < 8; nt++) {
                int n = nBase + wn * 64 + nt * 8 + tg * 2;
                float f0 = acc[mt][nt][half * 2 + 0];
                float f1 = acc[mt][nt][half * 2 + 1];
                if (mode == 0) {
                    float2 v; v.x = f0; v.y = f1;
                    *(float2*)&Cf[(size_t)m * DM + n] = v;
                } else {
                    int b = m >> 11;
                    int s = m & 2047;
                    int h = n >> 6;
                    int d = n & 63;
                    size_t addr = ((size_t)((b * HEADS + h) * S_LEN) + s) * DH + d;
                    if (mode == 1) {
                        uint32_t hi, lo;
                        split2h(f0, f1, hi, lo);
                        *(uint32_t*)&Chi[addr] = hi;
                        *(uint32_t*)&Clo[addr] = lo;
                    } else {
                        *(uint32_t*)&Chi[addr] = pack_h2(f0, f1);
                    }
                }
            }
        }
    }
}

// QKV projections in one launch: grid (8, 64, 3)
__global__ __launch_bounds__(256) void qkv_gemm()
{
    extern __shared__ __align__(1024) char smem[];
    const uint32_t sb = smem_to_u32(smem);
    const int z = blockIdx.z;
    __half* Chi = (z == 0) ? g_Qhi : (z == 1) ? g_Kh : g_Vh;
    __half* Clo = g_Qlo;
    gemm_body(g_Xhi, g_Xlo, g_Wh[z], nullptr, Chi, Clo,
              (z == 0) ? 1 : 2, blockIdx.y * 128, blockIdx.x * 128, sb);
}

// Output projection: fp32 into d_out
__global__ __launch_bounds__(256) void out_gemm(float* __restrict__ Cf)
{
    extern __shared__ __align__(1024) char smem[];
    const uint32_t sb = smem_to_u32(smem);
    gemm_body(g_Ahi, g_Alo, g_Wh[3], Cf, nullptr, nullptr,
              0, blockIdx.y * 128, blockIdx.x * 128, sb);
}

// ---------------------------------------------------------------------------
// HMMA flash attention (causal, online softmax, fp16 2-product both matmuls).
// Block: 256 threads (8 warps), 128 q-rows. kt loop over 64-row K/V tiles.
// SMEM: Qhi 16K | Qlo 16K | 2 stages x (Kh 8K | Vh 8K) = 64KB total.
// ---------------------------------------------------------------------------
#define FS_QB    32768
#define FS_STAGE 16384
#define FS_TOTAL (FS_QB + 2 * FS_STAGE)   // 65536

__global__ __launch_bounds__(256) void flash_mma_kernel()
{
    extern __shared__ __align__(1024) char smem[];
    const uint32_t sb = smem_to_u32(smem);
    const int tid  = threadIdx.x;
    const int wid  = tid >> 5;
    const int lane = tid & 31;
    const int g    = lane >> 2;
    const int tg   = lane & 3;
    const int l15  = lane & 15;
    const int khalf = ((lane >> 4) & 1) * 16;

    const int qt = (gridDim.x - 1) - blockIdx.x;   // heavy blocks first
    const int bh = blockIdx.y;
    const int qtBase = qt * 128;
    const int ktmax  = qt * 2 + 1;

    const size_t headBase = (size_t)bh * S_LEN * DH;

    // ---- load Q (hi, lo) once ----
    {
        const __half* qsrc[2] = { g_Qhi + headBase + (size_t)qtBase * DH,
                                  g_Qlo + headBase + (size_t)qtBase * DH };
#pragma unroll
        for (int t = 0; t < 2; t++) {
#pragma unroll
            for (int r = 0; r < 4; r++) {
                int unit = r * 256 + tid;     // 0..1023
                int row  = unit >> 3;         // 0..127
                int c16  = unit & 7;
                const char* gp = (const char*)(qsrc[t] + (size_t)row * DH) + c16 * 16;
                uint32_t so = sb + t * 16384 + SW128(row * 128 + c16 * 16);
                CP_ASYNC16(so, gp);
            }
        }
        CP_COMMIT();
    }

    const __half* kvsrc[2] = { g_Kh + headBase, g_Vh + headBase };

    auto load_kv = [&](int kt, int buf) {
        const uint32_t st = sb + FS_QB + buf * FS_STAGE;
        const size_t kvoff = (size_t)kt * 64 * DH;
#pragma unroll
        for (int t = 0; t < 2; t++) {
            const __half* base = kvsrc[t] + kvoff;
#pragma unroll
            for (int r = 0; r < 2; r++) {
                int unit = r * 256 + tid;     // 0..511
                int row  = unit >> 3;         // 0..63
                int c16  = unit & 7;
                const char* gp = (const char*)(base + (size_t)row * DH) + c16 * 16;
                uint32_t so = st + t * 8192 + SW128(row * 128 + c16 * 16);
                CP_ASYNC16(so, gp);
            }
        }
        CP_COMMIT();
    };

    load_kv(0, 0);

    uint32_t qhi[4][4], qlo[4][4];
    float o[8][4];
    float m_i[2] = { -1e30f, -1e30f };
    float l_i[2] = { 0.0f, 0.0f };
#pragma unroll
    for (int dt = 0; dt < 8; dt++)
#pragma unroll
        for (int r = 0; r < 4; r++) o[dt][r] = 0.0f;

    const float C1 = 0.18033688011112042f;    // log2(e) / sqrt(64)

    for (int kt = 0; kt <= ktmax; kt++) {
        if (kt < ktmax) load_kv(kt + 1, (kt + 1) & 1);
        if (kt < ktmax) asm volatile("cp.async.wait_group 1;" ::: "memory");
        else            asm volatile("cp.async.wait_group 0;" ::: "memory");
        __syncthreads();

        if (kt == 0) {
#pragma unroll
            for (int ks = 0; ks < 4; ks++) {
                int row = wid * 16 + l15;
                uint32_t off = SW128(row * 128 + ks * 32 + khalf);
                LDSM_X4(qhi[ks][0], qhi[ks][1], qhi[ks][2], qhi[ks][3], sb + off);
                LDSM_X4(qlo[ks][0], qlo[ks][1], qlo[ks][2], qlo[ks][3], sb + 16384 + off);
            }
        }

        const uint32_t st  = sb + FS_QB + (kt & 1) * FS_STAGE;
        const uint32_t KhB = st;
        const uint32_t VhB = st + 8192;

        // ---- S = Q K^T (2 products) ----
        float sacc[8][4];
#pragma unroll
        for (int nt = 0; nt < 8; nt++)
#pragma unroll
            for (int r = 0; r < 4; r++) sacc[nt][r] = 0.0f;

#pragma unroll
        for (int ks = 0; ks < 4; ks++) {
            const int kb = ks * 32 + khalf;
            uint32_t kh[8][2];
#pragma unroll
            for (int nq = 0; nq < 4; nq++) {
                int row = nq * 16 + l15;
                uint32_t off = SW128(row * 128 + kb);
                uint32_t r0, r1, r2, r3;
                LDSM_X4(r0, r1, r2, r3, KhB + off);
                kh[2 * nq][0] = r0; kh[2 * nq][1] = r2;
                kh[2 * nq + 1][0] = r1; kh[2 * nq + 1][1] = r3;
            }
#pragma unroll
            for (int nt = 0; nt < 8; nt++) {
                MMA_F16(sacc[nt], qhi[ks], kh[nt]);
                MMA_F16(sacc[nt], qlo[ks], kh[nt]);
            }
        }

        // ---- causal mask ----
        if (kt >= 2 * qt) {
            const int q0 = qtBase + wid * 16 + g;
            const int kcb = kt * 64;
#pragma unroll
            for (int nt = 0; nt < 8; nt++) {
                int kc = kcb + nt * 8 + tg * 2;
                if (kc     > q0)     sacc[nt][0] = -1e30f;
                if (kc + 1 > q0)     sacc[nt][1] = -1e30f;
                if (kc     > q0 + 8) sacc[nt][2] = -1e30f;
                if (kc + 1 > q0 + 8) sacc[nt][3] = -1e30f;
            }
        }

        // ---- online softmax ----
#pragma unroll
        for (int i = 0; i < 2; i++) {
            float mx = -1e30f;
#pragma unroll
            for (int nt = 0; nt < 8; nt++) {
                mx = fmaxf(mx, sacc[nt][2 * i]);
                mx = fmaxf(mx, sacc[nt][2 * i + 1]);
            }
            mx = fmaxf(mx, __shfl_xor_sync(0xffffffffu, mx, 1));
            mx = fmaxf(mx, __shfl_xor_sync(0xffffffffu, mx, 2));
            float mnew = fmaxf(m_i[i], mx);
            float corr = ex2f((m_i[i] - mnew) * C1);
            m_i[i] = mnew;
            float sum = 0.0f;
#pragma unroll
            for (int nt = 0; nt < 8; nt++) {
#pragma unroll
                for (int j = 0; j < 2; j++) {
                    float p = ex2f((sacc[nt][2 * i + j] - mnew) * C1);
                    sacc[nt][2 * i + j] = p;
                    sum += p;
                }
            }
            sum += __shfl_xor_sync(0xffffffffu, sum, 1);
            sum += __shfl_xor_sync(0xffffffffu, sum, 2);
            l_i[i] = l_i[i] * corr + sum;
#pragma unroll
            for (int dt = 0; dt < 8; dt++) {
                o[dt][2 * i]     *= corr;
                o[dt][2 * i + 1] *= corr;
            }
        }

        // ---- P fragments (fp16 hi/lo) ----
        uint32_t phi[4][4], plo[4][4];
#pragma unroll
        for (int ks = 0; ks < 4; ks++) {
            split2h(sacc[2 * ks][0],     sacc[2 * ks][1],     phi[ks][0], plo[ks][0]);
            split2h(sacc[2 * ks][2],     sacc[2 * ks][3],     phi[ks][1], plo[ks][1]);
            split2h(sacc[2 * ks + 1][0], sacc[2 * ks + 1][1], phi[ks][2], plo[ks][2]);
            split2h(sacc[2 * ks + 1][2], sacc[2 * ks + 1][3], phi[ks][3], plo[ks][3]);
        }

        // ---- O += P V (2 products) ----
#pragma unroll
        for (int ks = 0; ks < 4; ks++) {
            uint32_t vh[8][2];
#pragma unroll
            for (int dp = 0; dp < 4; dp++) {
                uint32_t off = SW128((ks * 16 + l15) * 128 + dp * 32 + khalf);
                uint32_t r0, r1, r2, r3;
                LDSM_X4_T(r0, r1, r2, r3, VhB + off);
                vh[2 * dp][0] = r0; vh[2 * dp][1] = r1;
                vh[2 * dp + 1][0] = r2; vh[2 * dp + 1][1] = r3;
            }
#pragma unroll
            for (int dt = 0; dt < 8; dt++) {
                MMA_F16(o[dt], phi[ks], vh[dt]);
                MMA_F16(o[dt], plo[ks], vh[dt]);
            }
        }

        __syncthreads();
    }

    // ---- epilogue: O/l -> fp16 hi/lo into [B,S,DM] ----
    const int b = bh >> 4;
    const int h = bh & 15;
#pragma unroll
    for (int i = 0; i < 2; i++) {
        float inv = 1.0f / l_i[i];
        int srow = qtBase + wid * 16 + g + 8 * i;
        size_t rowaddr = ((size_t)(b * S_LEN + srow)) * DM + h * 64;
#pragma unroll
        for (int dt = 0; dt < 8; dt++) {
            float f0 = o[dt][2 * i]     * inv;
            float f1 = o[dt][2 * i + 1] * inv;
            uint32_t hi, lo;
            split2h(f0, f1, hi, lo);
            size_t addr = rowaddr + dt * 8 + tg * 2;
            *(uint32_t*)&g_Ahi[addr] = hi;
            *(uint32_t*)&g_Alo[addr] = lo;
        }
    }
}

// ---------------------------------------------------------------------------
// Launch
// ---------------------------------------------------------------------------
extern "C" void kernel_launch(void* const* d_in, const int* in_sizes, int n_in,
                              void* d_out, int out_size)
{
    const float* X  = (const float*)d_in[0];
    const float* WQ = (const float*)d_in[1];
    const float* WK = (const float*)d_in[2];
    const float* WV = (const float*)d_in[3];
    const float* WO = (const float*)d_in[4];
    float* out = (float*)d_out;

    const int smem_gemm = 2 * STAGE_B;   // 98304
    cudaFuncSetAttribute(qkv_gemm,
                         cudaFuncAttributeMaxDynamicSharedMemorySize, smem_gemm);
    cudaFuncSetAttribute(out_gemm,
                         cudaFuncAttributeMaxDynamicSharedMemorySize, smem_gemm);
    cudaFuncSetAttribute(flash_mma_kernel,
                         cudaFuncAttributeMaxDynamicSharedMemorySize, FS_TOTAL);

    splitX_kernel<<<4096, 256>>>((const float4*)X, MROWS * DM / 4);
    convW_kernel<<<dim3(1024, 1, 4), 256>>>((const float4*)WQ, (const float4*)WK,
                                            (const float4*)WV, (const float4*)WO,
                                            DM * DM / 4);

    qkv_gemm<<<dim3(DM / 128, MROWS / 128, 3), 256, smem_gemm>>>();

    flash_mma_kernel<<<dim3(S_LEN / 128, BATCH * HEADS), 256, FS_TOTAL>>>();

    out_gemm<<<dim3(DM / 128, MROWS / 128), 256, smem_gemm>>>(out);
}

// round 6
// speedup vs baseline: 8.0746x; 1.8272x over previous
#include <cuda_runtime.h>
#include <cuda_fp16.h>
#include <cstdint>

// Problem constants
#define BATCH 4
#define S_LEN 2048
#define HEADS 16
#define DH    64
#define DM    1024
#define MROWS (BATCH * S_LEN)   // 8192
#define HS    (BATCH * HEADS * S_LEN * DH)   // 8388608

// ---------------------------------------------------------------------------
// Device scratch (fp16, rn-truncated — 1-product everywhere)
// ---------------------------------------------------------------------------
__device__ __half g_Xh[MROWS * DM];
__device__ __half g_Wh[4][DM * DM];
__device__ __half g_Qh[HS];                  // [B,H,S,Dh]
__device__ __half g_Kh[HS];
__device__ __half g_Vh[HS];
__device__ __half g_Ah[MROWS * DM];          // attn out [B,S,H*Dh]

// ---------------------------------------------------------------------------
// PTX helpers
// ---------------------------------------------------------------------------
__device__ __forceinline__ uint32_t smem_to_u32(const void* p) {
    uint32_t a;
    asm("{ .reg .u64 t; cvta.to.shared.u64 t, %1; cvt.u32.u64 %0, t; }"
        : "=r"(a) : "l"(p));
    return a;
}

#define CP_ASYNC16(smem_u32, gptr) \
    asm volatile("cp.async.cg.shared.global [%0], [%1], 16;" \
                 :: "r"(smem_u32), "l"(__cvta_generic_to_global(gptr)) : "memory")
#define CP_COMMIT()  asm volatile("cp.async.commit_group;" ::: "memory")

#define LDSM_X4(r0, r1, r2, r3, addr) \
    asm volatile("ldmatrix.sync.aligned.m8n8.x4.shared.b16 {%0,%1,%2,%3}, [%4];" \
                 : "=r"(r0), "=r"(r1), "=r"(r2), "=r"(r3) : "r"(addr))

#define LDSM_X4_T(r0, r1, r2, r3, addr) \
    asm volatile("ldmatrix.sync.aligned.m8n8.x4.trans.shared.b16 {%0,%1,%2,%3}, [%4];" \
                 : "=r"(r0), "=r"(r1), "=r"(r2), "=r"(r3) : "r"(addr))

#define MMA_F16(d, a, b) \
    asm volatile("mma.sync.aligned.m16n8k16.row.col.f32.f16.f16.f32 " \
                 "{%0,%1,%2,%3}, {%4,%5,%6,%7}, {%8,%9}, {%0,%1,%2,%3};" \
                 : "+f"((d)[0]), "+f"((d)[1]), "+f"((d)[2]), "+f"((d)[3]) \
                 : "r"((a)[0]), "r"((a)[1]), "r"((a)[2]), "r"((a)[3]), \
                   "r"((b)[0]), "r"((b)[1]))

#define SW128(off) ((off) ^ (((off) >> 3) & 0x70))

__device__ __forceinline__ float ex2f(float x) {
    float r;
    asm("ex2.approx.ftz.f32 %0, %1;" : "=f"(r) : "f"(x));
    return r;
}

__device__ __forceinline__ uint32_t pack_h2(float a, float b) {
    __half2 h = __floats2half2_rn(a, b);
    return *(uint32_t*)&h;
}

// ---------------------------------------------------------------------------
// fp32 -> fp16 conversion kernels
// ---------------------------------------------------------------------------
__global__ __launch_bounds__(256) void convX_kernel(const float4* __restrict__ x, int n4)
{
    uint32_t* dst = (uint32_t*)g_Xh;
    for (int i = blockIdx.x * blockDim.x + threadIdx.x; i < n4;
         i += gridDim.x * blockDim.x) {
        float4 v = x[i];
        dst[2 * i]     = pack_h2(v.x, v.y);
        dst[2 * i + 1] = pack_h2(v.z, v.w);
    }
}

__global__ __launch_bounds__(256) void convW_kernel(const float4* __restrict__ w0,
                                                    const float4* __restrict__ w1,
                                                    const float4* __restrict__ w2,
                                                    const float4* __restrict__ w3,
                                                    int n4)
{
    const int z = blockIdx.z;
    const float4* src = (z == 0) ? w0 : (z == 1) ? w1 : (z == 2) ? w2 : w3;
    uint32_t* dst = (uint32_t*)g_Wh[z];
    for (int i = blockIdx.x * blockDim.x + threadIdx.x; i < n4;
         i += gridDim.x * blockDim.x) {
        float4 v = src[i];
        dst[2 * i]     = pack_h2(v.x, v.y);
        dst[2 * i + 1] = pack_h2(v.z, v.w);
    }
}

// ---------------------------------------------------------------------------
// fp16 1-product HMMA GEMM body:
//   C[128x128 tile] of A[M,K=1024] @ W[N,K]^T
// Tile 128x128, K-chunk 64 (128B rows, SW128), cp.async double-buffered.
// Stage: Ah 16K | Wh 16K = 32KB; 2 stages = 64KB.
// mode 0: fp32 row-major. mode 1: fp16 scatter to [B,H,S,Dh].
// ---------------------------------------------------------------------------
#define TILE_B   16384
#define STAGE_B  (2 * TILE_B)

__device__ __forceinline__ void gemm_body(const __half* __restrict__ Ah,
                                          const __half* __restrict__ Wh,
                                          float* __restrict__ Cf,
                                          __half* __restrict__ Ch,
                                          int mode, int mBase, int nBase,
                                          uint32_t sb)
{
    const int tid  = threadIdx.x;
    const int wid  = tid >> 5;
    const int lane = tid & 31;
    const int wm = wid & 3;
    const int wn = wid >> 2;
    const int l15   = lane & 15;
    const int khalf = ((lane >> 4) & 1) * 16;

    const char* srcs[2] = {
        (const char*)(Ah + (size_t)mBase * DM),
        (const char*)(Wh + (size_t)nBase * DM)
    };

    float acc[2][8][4];
#pragma unroll
    for (int mt = 0; mt < 2; mt++)
#pragma unroll
        for (int nt = 0; nt < 8; nt++)
#pragma unroll
            for (int r = 0; r < 4; r++) acc[mt][nt][r] = 0.0f;

    auto load_stage = [&](int ic, int buf) {
        const uint32_t stage = sb + buf * STAGE_B;
#pragma unroll
        for (int t = 0; t < 2; t++) {
            const char* src = srcs[t];
#pragma unroll
            for (int r = 0; r < 4; r++) {
                int unit = r * 256 + tid;
                int row  = unit >> 3;
                int c16  = unit & 7;
                const char* g = src + (size_t)row * (DM * 2) + ic * 128 + c16 * 16;
                uint32_t so = stage + t * TILE_B + SW128(row * 128 + c16 * 16);
                CP_ASYNC16(so, g);
            }
        }
        CP_COMMIT();
    };

    load_stage(0, 0);

    for (int ic = 0; ic < 16; ic++) {
        if (ic < 15) load_stage(ic + 1, (ic + 1) & 1);
        if (ic < 15) asm volatile("cp.async.wait_group 1;" ::: "memory");
        else         asm volatile("cp.async.wait_group 0;" ::: "memory");
        __syncthreads();

        const uint32_t stage = sb + (ic & 1) * STAGE_B;
        const uint32_t aB = stage;
        const uint32_t wB = stage + TILE_B;

#pragma unroll
        for (int ks = 0; ks < 4; ks++) {
            const int kb = ks * 32 + khalf;

            uint32_t ah[2][4];
#pragma unroll
            for (int mt = 0; mt < 2; mt++) {
                int row = wm * 32 + mt * 16 + l15;
                uint32_t off = SW128(row * 128 + kb);
                LDSM_X4(ah[mt][0], ah[mt][1], ah[mt][2], ah[mt][3], aB + off);
            }

            uint32_t bh[8][2];
#pragma unroll
            for (int nq = 0; nq < 4; nq++) {
                int row = wn * 64 + nq * 16 + l15;
                uint32_t off = SW128(row * 128 + kb);
                uint32_t r0, r1, r2, r3;
                LDSM_X4(r0, r1, r2, r3, wB + off);
                bh[2 * nq][0] = r0; bh[2 * nq][1] = r2;
                bh[2 * nq + 1][0] = r1; bh[2 * nq + 1][1] = r3;
            }

#pragma unroll
            for (int mt = 0; mt < 2; mt++)
#pragma unroll
                for (int nt = 0; nt < 8; nt++)
                    MMA_F16(acc[mt][nt], ah[mt], bh[nt]);
        }
        __syncthreads();
    }

    // epilogue
    const int groupID = lane >> 2;
    const int tg      = lane & 3;
#pragma unroll
    for (int mt = 0; mt < 2; mt++) {
#pragma unroll
        for (int half = 0; half < 2; half++) {
            int m = mBase + wm * 32 + mt * 16 + groupID + half * 8;
#pragma unroll
            for (int nt = 0; nt < 8; nt++) {
                int n = nBase + wn * 64 + nt * 8 + tg * 2;
                float f0 = acc[mt][nt][half * 2 + 0];
                float f1 = acc[mt][nt][half * 2 + 1];
                if (mode == 0) {
                    float2 v; v.x = f0; v.y = f1;
                    *(float2*)&Cf[(size_t)m * DM + n] = v;
                } else {
                    int b = m >> 11;
                    int s = m & 2047;
                    int h = n >> 6;
                    int d = n & 63;
                    size_t addr = ((size_t)((b * HEADS + h) * S_LEN) + s) * DH + d;
                    *(uint32_t*)&Ch[addr] = pack_h2(f0, f1);
                }
            }
        }
    }
}

// QKV projections in one launch: grid (8, 64, 3)
__global__ __launch_bounds__(256, 2) void qkv_gemm()
{
    extern __shared__ __align__(1024) char smem[];
    const uint32_t sb = smem_to_u32(smem);
    const int z = blockIdx.z;
    __half* Ch = (z == 0) ? g_Qh : (z == 1) ? g_Kh : g_Vh;
    gemm_body(g_Xh, g_Wh[z], nullptr, Ch, 1,
              blockIdx.y * 128, blockIdx.x * 128, sb);
}

// Output projection: fp32 into d_out
__global__ __launch_bounds__(256, 2) void out_gemm(float* __restrict__ Cf)
{
    extern __shared__ __align__(1024) char smem[];
    const uint32_t sb = smem_to_u32(smem);
    gemm_body(g_Ah, g_Wh[3], Cf, nullptr, 0,
              blockIdx.y * 128, blockIdx.x * 128, sb);
}

// ---------------------------------------------------------------------------
// HMMA flash attention (causal, online softmax, fp16 1-product matmuls).
// Block: 256 threads (8 warps), 128 q-rows. kt loop over 64-row K/V tiles.
// SMEM: Qh 16K | 2 stages x (Kh 8K | Vh 8K) = 48KB total.
// ---------------------------------------------------------------------------
#define FS_QB    16384
#define FS_STAGE 16384
#define FS_TOTAL (FS_QB + 2 * FS_STAGE)   // 49152

__global__ __launch_bounds__(256, 2) void flash_mma_kernel()
{
    extern __shared__ __align__(1024) char smem[];
    const uint32_t sb = smem_to_u32(smem);
    const int tid  = threadIdx.x;
    const int wid  = tid >> 5;
    const int lane = tid & 31;
    const int g    = lane >> 2;
    const int tg   = lane & 3;
    const int l15  = lane & 15;
    const int khalf = ((lane >> 4) & 1) * 16;

    const int qt = (gridDim.x - 1) - blockIdx.x;   // heavy blocks first
    const int bh = blockIdx.y;
    const int qtBase = qt * 128;
    const int ktmax  = qt * 2 + 1;

    const size_t headBase = (size_t)bh * S_LEN * DH;

    // ---- load Q once ----
    {
        const __half* qsrc = g_Qh + headBase + (size_t)qtBase * DH;
#pragma unroll
        for (int r = 0; r < 4; r++) {
            int unit = r * 256 + tid;     // 0..1023
            int row  = unit >> 3;         // 0..127
            int c16  = unit & 7;
            const char* gp = (const char*)(qsrc + (size_t)row * DH) + c16 * 16;
            uint32_t so = sb + SW128(row * 128 + c16 * 16);
            CP_ASYNC16(so, gp);
        }
        CP_COMMIT();
    }

    const __half* kvsrc[2] = { g_Kh + headBase, g_Vh + headBase };

    auto load_kv = [&](int kt, int buf) {
        const uint32_t st = sb + FS_QB + buf * FS_STAGE;
        const size_t kvoff = (size_t)kt * 64 * DH;
#pragma unroll
        for (int t = 0; t < 2; t++) {
            const __half* base = kvsrc[t] + kvoff;
#pragma unroll
            for (int r = 0; r < 2; r++) {
                int unit = r * 256 + tid;     // 0..511
                int row  = unit >> 3;         // 0..63
                int c16  = unit & 7;
                const char* gp = (const char*)(base + (size_t)row * DH) + c16 * 16;
                uint32_t so = st + t * 8192 + SW128(row * 128 + c16 * 16);
                CP_ASYNC16(so, gp);
            }
        }
        CP_COMMIT();
    };

    load_kv(0, 0);

    uint32_t qh[4][4];
    float o[8][4];
    float m_i[2] = { -1e30f, -1e30f };
    float l_i[2] = { 0.0f, 0.0f };
#pragma unroll
    for (int dt = 0; dt < 8; dt++)
#pragma unroll
        for (int r = 0; r < 4; r++) o[dt][r] = 0.0f;

    const float C1 = 0.18033688011112042f;    // log2(e) / sqrt(64)

    for (int kt = 0; kt <= ktmax; kt++) {
        if (kt < ktmax) load_kv(kt + 1, (kt + 1) & 1);
        if (kt < ktmax) asm volatile("cp.async.wait_group 1;" ::: "memory");
        else            asm volatile("cp.async.wait_group 0;" ::: "memory");
        __syncthreads();

        if (kt == 0) {
#pragma unroll
            for (int ks = 0; ks < 4; ks++) {
                int row = wid * 16 + l15;
                uint32_t off = SW128(row * 128 + ks * 32 + khalf);
                LDSM_X4(qh[ks][0], qh[ks][1], qh[ks][2], qh[ks][3], sb + off);
            }
        }

        const uint32_t st  = sb + FS_QB + (kt & 1) * FS_STAGE;
        const uint32_t KhB = st;
        const uint32_t VhB = st + 8192;

        // ---- S = Q K^T ----
        float sacc[8][4];
#pragma unroll
        for (int nt = 0; nt < 8; nt++)
#pragma unroll
            for (int r = 0; r < 4; r++) sacc[nt][r] = 0.0f;

#pragma unroll
        for (int ks = 0; ks < 4; ks++) {
            const int kb = ks * 32 + khalf;
            uint32_t kh[8][2];
#pragma unroll
            for (int nq = 0; nq < 4; nq++) {
                int row = nq * 16 + l15;
                uint32_t off = SW128(row * 128 + kb);
                uint32_t r0, r1, r2, r3;
                LDSM_X4(r0, r1, r2, r3, KhB + off);
                kh[2 * nq][0] = r0; kh[2 * nq][1] = r2;
                kh[2 * nq + 1][0] = r1; kh[2 * nq + 1][1] = r3;
            }
#pragma unroll
            for (int nt = 0; nt < 8; nt++)
                MMA_F16(sacc[nt], qh[ks], kh[nt]);
        }

        // ---- causal mask ----
        if (kt >= 2 * qt) {
            const int q0 = qtBase + wid * 16 + g;
            const int kcb = kt * 64;
#pragma unroll
            for (int nt = 0; nt < 8; nt++) {
                int kc = kcb + nt * 8 + tg * 2;
                if (kc     > q0)     sacc[nt][0] = -1e30f;
                if (kc + 1 > q0)     sacc[nt][1] = -1e30f;
                if (kc     > q0 + 8) sacc[nt][2] = -1e30f;
                if (kc + 1 > q0 + 8) sacc[nt][3] = -1e30f;
            }
        }

        // ---- online softmax ----
#pragma unroll
        for (int i = 0; i < 2; i++) {
            float mx = -1e30f;
#pragma unroll
            for (int nt = 0; nt < 8; nt++) {
                mx = fmaxf(mx, sacc[nt][2 * i]);
                mx = fmaxf(mx, sacc[nt][2 * i + 1]);
            }
            mx = fmaxf(mx, __shfl_xor_sync(0xffffffffu, mx, 1));
            mx = fmaxf(mx, __shfl_xor_sync(0xffffffffu, mx, 2));
            float mnew = fmaxf(m_i[i], mx);
            float corr = ex2f((m_i[i] - mnew) * C1);
            m_i[i] = mnew;
            float sum = 0.0f;
#pragma unroll
            for (int nt = 0; nt < 8; nt++) {
#pragma unroll
                for (int j = 0; j < 2; j++) {
                    float p = ex2f((sacc[nt][2 * i + j] - mnew) * C1);
                    sacc[nt][2 * i + j] = p;
                    sum += p;
                }
            }
            sum += __shfl_xor_sync(0xffffffffu, sum, 1);
            sum += __shfl_xor_sync(0xffffffffu, sum, 2);
            l_i[i] = l_i[i] * corr + sum;
#pragma unroll
            for (int dt = 0; dt < 8; dt++) {
                o[dt][2 * i]     *= corr;
                o[dt][2 * i + 1] *= corr;
            }
        }

        // ---- P fragments (fp16, rn-truncated) ----
        uint32_t ph[4][4];
#pragma unroll
        for (int ks = 0; ks < 4; ks++) {
            ph[ks][0] = pack_h2(sacc[2 * ks][0],     sacc[2 * ks][1]);
            ph[ks][1] = pack_h2(sacc[2 * ks][2],     sacc[2 * ks][3]);
            ph[ks][2] = pack_h2(sacc[2 * ks + 1][0], sacc[2 * ks + 1][1]);
            ph[ks][3] = pack_h2(sacc[2 * ks + 1][2], sacc[2 * ks + 1][3]);
        }

        // ---- O += P V ----
#pragma unroll
        for (int ks = 0; ks < 4; ks++) {
            uint32_t vh[8][2];
#pragma unroll
            for (int dp = 0; dp < 4; dp++) {
                uint32_t off = SW128((ks * 16 + l15) * 128 + dp * 32 + khalf);
                uint32_t r0, r1, r2, r3;
                LDSM_X4_T(r0, r1, r2, r3, VhB + off);
                vh[2 * dp][0] = r0; vh[2 * dp][1] = r1;
                vh[2 * dp + 1][0] = r2; vh[2 * dp + 1][1] = r3;
            }
#pragma unroll
            for (int dt = 0; dt < 8; dt++)
                MMA_F16(o[dt], ph[ks], vh[dt]);
        }

        __syncthreads();
    }

    // ---- epilogue: O/l -> fp16 into [B,S,DM] ----
    const int b = bh >> 4;
    const int h = bh & 15;
#pragma unroll
    for (int i = 0; i < 2; i++) {
        float inv = 1.0f / l_i[i];
        int srow = qtBase + wid * 16 + g + 8 * i;
        size_t rowaddr = ((size_t)(b * S_LEN + srow)) * DM + h * 64;
#pragma unroll
        for (int dt = 0; dt < 8; dt++) {
            float f0 = o[dt][2 * i]     * inv;
            float f1 = o[dt][2 * i + 1] * inv;
            size_t addr = rowaddr + dt * 8 + tg * 2;
            *(uint32_t*)&g_Ah[addr] = pack_h2(f0, f1);
        }
    }
}

// ---------------------------------------------------------------------------
// Launch
// ---------------------------------------------------------------------------
extern "C" void kernel_launch(void* const* d_in, const int* in_sizes, int n_in,
                              void* d_out, int out_size)
{
    const float* X  = (const float*)d_in[0];
    const float* WQ = (const float*)d_in[1];
    const float* WK = (const float*)d_in[2];
    const float* WV = (const float*)d_in[3];
    const float* WO = (const float*)d_in[4];
    float* out = (float*)d_out;

    const int smem_gemm = 2 * STAGE_B;   // 65536
    cudaFuncSetAttribute(qkv_gemm,
                         cudaFuncAttributeMaxDynamicSharedMemorySize, smem_gemm);
    cudaFuncSetAttribute(out_gemm,
                         cudaFuncAttributeMaxDynamicSharedMemorySize, smem_gemm);
    cudaFuncSetAttribute(flash_mma_kernel,
                         cudaFuncAttributeMaxDynamicSharedMemorySize, FS_TOTAL);

    convX_kernel<<<4096, 256>>>((const float4*)X, MROWS * DM / 4);
    convW_kernel<<<dim3(1024, 1, 4), 256>>>((const float4*)WQ, (const float4*)WK,
                                            (const float4*)WV, (const float4*)WO,
                                            DM * DM / 4);

    qkv_gemm<<<dim3(DM / 128, MROWS / 128, 3), 256, smem_gemm>>>();

    flash_mma_kernel<<<dim3(S_LEN / 128, BATCH * HEADS), 256, FS_TOTAL>>>();

    out_gemm<<<dim3(DM / 128, MROWS / 128), 256, smem_gemm>>>(out);
}

// round 7
// speedup vs baseline: 8.2286x; 1.0191x over previous
#include <cuda_runtime.h>
#include <cuda_fp16.h>
#include <cstdint>

// Problem constants
#define BATCH 4
#define S_LEN 2048
#define HEADS 16
#define DH    64
#define DM    1024
#define MROWS (BATCH * S_LEN)   // 8192
#define HS    (BATCH * HEADS * S_LEN * DH)   // 8388608

// ---------------------------------------------------------------------------
// Device scratch (fp16, rn-truncated — 1-product everywhere)
// ---------------------------------------------------------------------------
__device__ __half g_Xh[MROWS * DM];
__device__ __half g_Wh[4][DM * DM];
__device__ __half g_Qh[HS];                  // [B,H,S,Dh]
__device__ __half g_Kh[HS];
__device__ __half g_Vh[HS];
__device__ __half g_Ah[MROWS * DM];          // attn out [B,S,H*Dh]

// ---------------------------------------------------------------------------
// PTX helpers
// ---------------------------------------------------------------------------
__device__ __forceinline__ uint32_t smem_to_u32(const void* p) {
    uint32_t a;
    asm("{ .reg .u64 t; cvta.to.shared.u64 t, %1; cvt.u32.u64 %0, t; }"
        : "=r"(a) : "l"(p));
    return a;
}

#define CP_ASYNC16(smem_u32, gptr) \
    asm volatile("cp.async.cg.shared.global [%0], [%1], 16;" \
                 :: "r"(smem_u32), "l"(__cvta_generic_to_global(gptr)) : "memory")
#define CP_COMMIT()  asm volatile("cp.async.commit_group;" ::: "memory")

#define LDSM_X4(r0, r1, r2, r3, addr) \
    asm volatile("ldmatrix.sync.aligned.m8n8.x4.shared.b16 {%0,%1,%2,%3}, [%4];" \
                 : "=r"(r0), "=r"(r1), "=r"(r2), "=r"(r3) : "r"(addr))

#define LDSM_X4_T(r0, r1, r2, r3, addr) \
    asm volatile("ldmatrix.sync.aligned.m8n8.x4.trans.shared.b16 {%0,%1,%2,%3}, [%4];" \
                 : "=r"(r0), "=r"(r1), "=r"(r2), "=r"(r3) : "r"(addr))

#define MMA_F16(d, a, b) \
    asm volatile("mma.sync.aligned.m16n8k16.row.col.f32.f16.f16.f32 " \
                 "{%0,%1,%2,%3}, {%4,%5,%6,%7}, {%8,%9}, {%0,%1,%2,%3};" \
                 : "+f"((d)[0]), "+f"((d)[1]), "+f"((d)[2]), "+f"((d)[3]) \
                 : "r"((a)[0]), "r"((a)[1]), "r"((a)[2]), "r"((a)[3]), \
                   "r"((b)[0]), "r"((b)[1]))

#define SW128(off) ((off) ^ (((off) >> 3) & 0x70))

__device__ __forceinline__ float ex2f(float x) {
    float r;
    asm("ex2.approx.ftz.f32 %0, %1;" : "=f"(r) : "f"(x));
    return r;
}

__device__ __forceinline__ uint32_t ex2h2(uint32_t x) {
    uint32_t r;
    asm("ex2.approx.f16x2 %0, %1;" : "=r"(r) : "r"(x));
    return r;
}

__device__ __forceinline__ uint32_t pack_h2(float a, float b) {
    __half2 h = __floats2half2_rn(a, b);
    return *(uint32_t*)&h;
}

// ---------------------------------------------------------------------------
// fp32 -> fp16 conversion kernels
// ---------------------------------------------------------------------------
__global__ __launch_bounds__(256) void convX_kernel(const float4* __restrict__ x, int n4)
{
    uint32_t* dst = (uint32_t*)g_Xh;
    for (int i = blockIdx.x * blockDim.x + threadIdx.x; i < n4;
         i += gridDim.x * blockDim.x) {
        float4 v = x[i];
        dst[2 * i]     = pack_h2(v.x, v.y);
        dst[2 * i + 1] = pack_h2(v.z, v.w);
    }
}

__global__ __launch_bounds__(256) void convW_kernel(const float4* __restrict__ w0,
                                                    const float4* __restrict__ w1,
                                                    const float4* __restrict__ w2,
                                                    const float4* __restrict__ w3,
                                                    int n4)
{
    const int z = blockIdx.z;
    const float4* src = (z == 0) ? w0 : (z == 1) ? w1 : (z == 2) ? w2 : w3;
    uint32_t* dst = (uint32_t*)g_Wh[z];
    for (int i = blockIdx.x * blockDim.x + threadIdx.x; i < n4;
         i += gridDim.x * blockDim.x) {
        float4 v = src[i];
        dst[2 * i]     = pack_h2(v.x, v.y);
        dst[2 * i + 1] = pack_h2(v.z, v.w);
    }
}

// ---------------------------------------------------------------------------
// fp16 1-product HMMA GEMM body (unchanged from R6 — near its roof)
// ---------------------------------------------------------------------------
#define TILE_B   16384
#define STAGE_B  (2 * TILE_B)

__device__ __forceinline__ void gemm_body(const __half* __restrict__ Ah,
                                          const __half* __restrict__ Wh,
                                          float* __restrict__ Cf,
                                          __half* __restrict__ Ch,
                                          int mode, int mBase, int nBase,
                                          uint32_t sb)
{
    const int tid  = threadIdx.x;
    const int wid  = tid >> 5;
    const int lane = tid & 31;
    const int wm = wid & 3;
    const int wn = wid >> 2;
    const int l15   = lane & 15;
    const int khalf = ((lane >> 4) & 1) * 16;

    const char* srcs[2] = {
        (const char*)(Ah + (size_t)mBase * DM),
        (const char*)(Wh + (size_t)nBase * DM)
    };

    float acc[2][8][4];
#pragma unroll
    for (int mt = 0; mt < 2; mt++)
#pragma unroll
        for (int nt = 0; nt < 8; nt++)
#pragma unroll
            for (int r = 0; r < 4; r++) acc[mt][nt][r] = 0.0f;

    auto load_stage = [&](int ic, int buf) {
        const uint32_t stage = sb + buf * STAGE_B;
#pragma unroll
        for (int t = 0; t < 2; t++) {
            const char* src = srcs[t];
#pragma unroll
            for (int r = 0; r < 4; r++) {
                int unit = r * 256 + tid;
                int row  = unit >> 3;
                int c16  = unit & 7;
                const char* g = src + (size_t)row * (DM * 2) + ic * 128 + c16 * 16;
                uint32_t so = stage + t * TILE_B + SW128(row * 128 + c16 * 16);
                CP_ASYNC16(so, g);
            }
        }
        CP_COMMIT();
    };

    load_stage(0, 0);

    for (int ic = 0; ic < 16; ic++) {
        if (ic < 15) load_stage(ic + 1, (ic + 1) & 1);
        if (ic < 15) asm volatile("cp.async.wait_group 1;" ::: "memory");
        else         asm volatile("cp.async.wait_group 0;" ::: "memory");
        __syncthreads();

        const uint32_t stage = sb + (ic & 1) * STAGE_B;
        const uint32_t aB = stage;
        const uint32_t wB = stage + TILE_B;

#pragma unroll
        for (int ks = 0; ks < 4; ks++) {
            const int kb = ks * 32 + khalf;

            uint32_t ah[2][4];
#pragma unroll
            for (int mt = 0; mt < 2; mt++) {
                int row = wm * 32 + mt * 16 + l15;
                uint32_t off = SW128(row * 128 + kb);
                LDSM_X4(ah[mt][0], ah[mt][1], ah[mt][2], ah[mt][3], aB + off);
            }

            uint32_t bh[8][2];
#pragma unroll
            for (int nq = 0; nq < 4; nq++) {
                int row = wn * 64 + nq * 16 + l15;
                uint32_t off = SW128(row * 128 + kb);
                uint32_t r0, r1, r2, r3;
                LDSM_X4(r0, r1, r2, r3, wB + off);
                bh[2 * nq][0] = r0; bh[2 * nq][1] = r2;
                bh[2 * nq + 1][0] = r1; bh[2 * nq + 1][1] = r3;
            }

#pragma unroll
            for (int mt = 0; mt < 2; mt++)
#pragma unroll
                for (int nt = 0; nt < 8; nt++)
                    MMA_F16(acc[mt][nt], ah[mt], bh[nt]);
        }
        __syncthreads();
    }

    // epilogue
    const int groupID = lane >> 2;
    const int tg      = lane & 3;
#pragma unroll
    for (int mt = 0; mt < 2; mt++) {
#pragma unroll
        for (int half = 0; half < 2; half++) {
            int m = mBase + wm * 32 + mt * 16 + groupID + half * 8;
#pragma unroll
            for (int nt = 0; nt < 8; nt++) {
                int n = nBase + wn * 64 + nt * 8 + tg * 2;
                float f0 = acc[mt][nt][half * 2 + 0];
                float f1 = acc[mt][nt][half * 2 + 1];
                if (mode == 0) {
                    float2 v; v.x = f0; v.y = f1;
                    *(float2*)&Cf[(size_t)m * DM + n] = v;
                } else {
                    int b = m >> 11;
                    int s = m & 2047;
                    int h = n >> 6;
                    int d = n & 63;
                    size_t addr = ((size_t)((b * HEADS + h) * S_LEN) + s) * DH + d;
                    *(uint32_t*)&Ch[addr] = pack_h2(f0, f1);
                }
            }
        }
    }
}

__global__ __launch_bounds__(256, 2) void qkv_gemm()
{
    extern __shared__ __align__(1024) char smem[];
    const uint32_t sb = smem_to_u32(smem);
    const int z = blockIdx.z;
    __half* Ch = (z == 0) ? g_Qh : (z == 1) ? g_Kh : g_Vh;
    gemm_body(g_Xh, g_Wh[z], nullptr, Ch, 1,
              blockIdx.y * 128, blockIdx.x * 128, sb);
}

__global__ __launch_bounds__(256, 2) void out_gemm(float* __restrict__ Cf)
{
    extern __shared__ __align__(1024) char smem[];
    const uint32_t sb = smem_to_u32(smem);
    gemm_body(g_Ah, g_Wh[3], Cf, nullptr, 0,
              blockIdx.y * 128, blockIdx.x * 128, sb);
}

// ---------------------------------------------------------------------------
// HMMA flash attention — fp16x2 softmax path.
// Block: 256 threads (8 warps), 128 q-rows. kt loop over 64-row K/V tiles.
// SMEM: Qh 16K | 2 stages x (Kh 8K | Vh 8K) = 48KB total.
// ---------------------------------------------------------------------------
#define FS_QB    16384
#define FS_STAGE 16384
#define FS_TOTAL (FS_QB + 2 * FS_STAGE)   // 49152

__global__ __launch_bounds__(256, 2) void flash_mma_kernel()
{
    extern __shared__ __align__(1024) char smem[];
    const uint32_t sb = smem_to_u32(smem);
    const int tid  = threadIdx.x;
    const int wid  = tid >> 5;
    const int lane = tid & 31;
    const int g    = lane >> 2;
    const int tg   = lane & 3;
    const int l15  = lane & 15;
    const int khalf = ((lane >> 4) & 1) * 16;

    const int qt = (gridDim.x - 1) - blockIdx.x;   // heavy blocks first
    const int bh = blockIdx.y;
    const int qtBase = qt * 128;
    const int ktmax  = qt * 2 + 1;

    const size_t headBase = (size_t)bh * S_LEN * DH;

    // ---- load Q once ----
    {
        const __half* qsrc = g_Qh + headBase + (size_t)qtBase * DH;
#pragma unroll
        for (int r = 0; r < 4; r++) {
            int unit = r * 256 + tid;     // 0..1023
            int row  = unit >> 3;         // 0..127
            int c16  = unit & 7;
            const char* gp = (const char*)(qsrc + (size_t)row * DH) + c16 * 16;
            uint32_t so = sb + SW128(row * 128 + c16 * 16);
            CP_ASYNC16(so, gp);
        }
        CP_COMMIT();
    }

    const __half* kvsrc[2] = { g_Kh + headBase, g_Vh + headBase };

    auto load_kv = [&](int kt, int buf) {
        const uint32_t st = sb + FS_QB + buf * FS_STAGE;
        const size_t kvoff = (size_t)kt * 64 * DH;
#pragma unroll
        for (int t = 0; t < 2; t++) {
            const __half* base = kvsrc[t] + kvoff;
#pragma unroll
            for (int r = 0; r < 2; r++) {
                int unit = r * 256 + tid;     // 0..511
                int row  = unit >> 3;         // 0..63
                int c16  = unit & 7;
                const char* gp = (const char*)(base + (size_t)row * DH) + c16 * 16;
                uint32_t so = st + t * 8192 + SW128(row * 128 + c16 * 16);
                CP_ASYNC16(so, gp);
            }
        }
        CP_COMMIT();
    };

    load_kv(0, 0);

    uint32_t qh[4][4];
    float o[8][4];
    float m_i[2] = { -1e30f, -1e30f };
    float l_p[2] = { 0.0f, 0.0f };   // per-thread partial row-sum (quad-reduced at end)
#pragma unroll
    for (int dt = 0; dt < 8; dt++)
#pragma unroll
        for (int r = 0; r < 4; r++) o[dt][r] = 0.0f;

    const float C1 = 0.18033688011112042f;    // log2(e) / sqrt(64)
    const __half2 c1h2 = __float2half2_rn(C1);

    for (int kt = 0; kt <= ktmax; kt++) {
        if (kt < ktmax) load_kv(kt + 1, (kt + 1) & 1);
        if (kt < ktmax) asm volatile("cp.async.wait_group 1;" ::: "memory");
        else            asm volatile("cp.async.wait_group 0;" ::: "memory");
        __syncthreads();

        if (kt == 0) {
#pragma unroll
            for (int ks = 0; ks < 4; ks++) {
                int row = wid * 16 + l15;
                uint32_t off = SW128(row * 128 + ks * 32 + khalf);
                LDSM_X4(qh[ks][0], qh[ks][1], qh[ks][2], qh[ks][3], sb + off);
            }
        }

        const uint32_t st  = sb + FS_QB + (kt & 1) * FS_STAGE;
        const uint32_t KhB = st;
        const uint32_t VhB = st + 8192;

        // ---- S = Q K^T ----
        float sacc[8][4];
#pragma unroll
        for (int nt = 0; nt < 8; nt++)
#pragma unroll
            for (int r = 0; r < 4; r++) sacc[nt][r] = 0.0f;

#pragma unroll
        for (int ks = 0; ks < 4; ks++) {
            const int kb = ks * 32 + khalf;
            uint32_t kh[8][2];
#pragma unroll
            for (int nq = 0; nq < 4; nq++) {
                int row = nq * 16 + l15;
                uint32_t off = SW128(row * 128 + kb);
                uint32_t r0, r1, r2, r3;
                LDSM_X4(r0, r1, r2, r3, KhB + off);
                kh[2 * nq][0] = r0; kh[2 * nq][1] = r2;
                kh[2 * nq + 1][0] = r1; kh[2 * nq + 1][1] = r3;
            }
#pragma unroll
            for (int nt = 0; nt < 8; nt++)
                MMA_F16(sacc[nt], qh[ks], kh[nt]);
        }

        // ---- causal mask ----
        if (kt >= 2 * qt) {
            const int q0 = qtBase + wid * 16 + g;
            const int kcb = kt * 64;
#pragma unroll
            for (int nt = 0; nt < 8; nt++) {
                int kc = kcb + nt * 8 + tg * 2;
                if (kc     > q0)     sacc[nt][0] = -1e30f;
                if (kc + 1 > q0)     sacc[nt][1] = -1e30f;
                if (kc     > q0 + 8) sacc[nt][2] = -1e30f;
                if (kc + 1 > q0 + 8) sacc[nt][3] = -1e30f;
            }
        }

        // ---- online softmax, fp16x2 path; pp[i][nt] = P fragments ----
        uint32_t pp[2][8];
#pragma unroll
        for (int i = 0; i < 2; i++) {
            // scores -> half2 (this is also the P pack)
            uint32_t th2[8];
#pragma unroll
            for (int nt = 0; nt < 8; nt++)
                th2[nt] = pack_h2(sacc[nt][2 * i], sacc[nt][2 * i + 1]);

            // row max via hmax2 tree (approx max is safe: cancels in o/l)
            __half2 mh = *(__half2*)&th2[0];
#pragma unroll
            for (int nt = 1; nt < 8; nt++)
                mh = __hmax2(mh, *(__half2*)&th2[nt]);
            float mx = fmaxf(__low2float(mh), __high2float(mh));
            mx = fmaxf(mx, __shfl_xor_sync(0xffffffffu, mx, 1));
            mx = fmaxf(mx, __shfl_xor_sync(0xffffffffu, mx, 2));

            float mnew = fmaxf(m_i[i], mx);
            float corr = ex2f((m_i[i] - mnew) * C1);
            m_i[i] = mnew;

            const __half2 bh2 = __float2half2_rn(-mnew * C1);
            __half2 hsum = __float2half2_rn(0.0f);
#pragma unroll
            for (int nt = 0; nt < 8; nt++) {
                __half2 arg = __hfma2(*(__half2*)&th2[nt], c1h2, bh2);
                uint32_t p = ex2h2(*(uint32_t*)&arg);
                pp[i][nt] = p;
                hsum = __hadd2(hsum, *(__half2*)&p);
            }
            l_p[i] = l_p[i] * corr + __low2float(hsum) + __high2float(hsum);
#pragma unroll
            for (int dt = 0; dt < 8; dt++) {
                o[dt][2 * i]     *= corr;
                o[dt][2 * i + 1] *= corr;
            }
        }

        // ---- P fragments ----
        uint32_t ph[4][4];
#pragma unroll
        for (int ks = 0; ks < 4; ks++) {
            ph[ks][0] = pp[0][2 * ks];
            ph[ks][1] = pp[1][2 * ks];
            ph[ks][2] = pp[0][2 * ks + 1];
            ph[ks][3] = pp[1][2 * ks + 1];
        }

        // ---- O += P V ----
#pragma unroll
        for (int ks = 0; ks < 4; ks++) {
            uint32_t vh[8][2];
#pragma unroll
            for (int dp = 0; dp < 4; dp++) {
                uint32_t off = SW128((ks * 16 + l15) * 128 + dp * 32 + khalf);
                uint32_t r0, r1, r2, r3;
                LDSM_X4_T(r0, r1, r2, r3, VhB + off);
                vh[2 * dp][0] = r0; vh[2 * dp][1] = r1;
                vh[2 * dp + 1][0] = r2; vh[2 * dp + 1][1] = r3;
            }
#pragma unroll
            for (int dt = 0; dt < 8; dt++)
                MMA_F16(o[dt], ph[ks], vh[dt]);
        }

        __syncthreads();
    }

    // ---- epilogue: quad-reduce l, O/l -> fp16 into [B,S,DM] ----
    const int b = bh >> 4;
    const int h = bh & 15;
#pragma unroll
    for (int i = 0; i < 2; i++) {
        float l = l_p[i];
        l += __shfl_xor_sync(0xffffffffu, l, 1);
        l += __shfl_xor_sync(0xffffffffu, l, 2);
        float inv = 1.0f / l;
        int srow = qtBase + wid * 16 + g + 8 * i;
        size_t rowaddr = ((size_t)(b * S_LEN + srow)) * DM + h * 64;
#pragma unroll
        for (int dt = 0; dt < 8; dt++) {
            float f0 = o[dt][2 * i]     * inv;
            float f1 = o[dt][2 * i + 1] * inv;
            size_t addr = rowaddr + dt * 8 + tg * 2;
            *(uint32_t*)&g_Ah[addr] = pack_h2(f0, f1);
        }
    }
}

// ---------------------------------------------------------------------------
// Launch
// ---------------------------------------------------------------------------
extern "C" void kernel_launch(void* const* d_in, const int* in_sizes, int n_in,
                              void* d_out, int out_size)
{
    const float* X  = (const float*)d_in[0];
    const float* WQ = (const float*)d_in[1];
    const float* WK = (const float*)d_in[2];
    const float* WV = (const float*)d_in[3];
    const float* WO = (const float*)d_in[4];
    float* out = (float*)d_out;

    const int smem_gemm = 2 * STAGE_B;   // 65536
    cudaFuncSetAttribute(qkv_gemm,
                         cudaFuncAttributeMaxDynamicSharedMemorySize, smem_gemm);
    cudaFuncSetAttribute(out_gemm,
                         cudaFuncAttributeMaxDynamicSharedMemorySize, smem_gemm);
    cudaFuncSetAttribute(flash_mma_kernel,
                         cudaFuncAttributeMaxDynamicSharedMemorySize, FS_TOTAL);

    convX_kernel<<<4096, 256>>>((const float4*)X, MROWS * DM / 4);
    convW_kernel<<<dim3(1024, 1, 4), 256>>>((const float4*)WQ, (const float4*)WK,
                                            (const float4*)WV, (const float4*)WO,
                                            DM * DM / 4);

    qkv_gemm<<<dim3(DM / 128, MROWS / 128, 3), 256, smem_gemm>>>();

    flash_mma_kernel<<<dim3(S_LEN / 128, BATCH * HEADS), 256, FS_TOTAL>>>();

    out_gemm<<<dim3(DM / 128, MROWS / 128), 256, smem_gemm>>>(out);
}

// round 10
// speedup vs baseline: 8.6260x; 1.0483x over previous
#include <cuda_runtime.h>
#include <cuda_fp16.h>
#include <cstdint>

// Problem constants
#define BATCH 4
#define S_LEN 2048
#define HEADS 16
#define DH    64
#define DM    1024
#define MROWS (BATCH * S_LEN)   // 8192
#define HS    (BATCH * HEADS * S_LEN * DH)   // 8388608

// ---------------------------------------------------------------------------
// Device scratch (fp16, rn-truncated — 1-product everywhere)
// ---------------------------------------------------------------------------
__device__ __half g_Xh[MROWS * DM];
__device__ __half g_Wh[4][DM * DM];
__device__ __half g_Qh[HS];                  // [B,H,S,Dh]
__device__ __half g_Kh[HS];
__device__ __half g_Vh[HS];
__device__ __half g_Ah[MROWS * DM];          // attn out [B,S,H*Dh]

// ---------------------------------------------------------------------------
// PTX helpers
// ---------------------------------------------------------------------------
__device__ __forceinline__ uint32_t smem_to_u32(const void* p) {
    uint32_t a;
    asm("{ .reg .u64 t; cvta.to.shared.u64 t, %1; cvt.u32.u64 %0, t; }"
        : "=r"(a) : "l"(p));
    return a;
}

#define CP_ASYNC16(smem_u32, gptr) \
    asm volatile("cp.async.cg.shared.global [%0], [%1], 16;" \
                 :: "r"(smem_u32), "l"(__cvta_generic_to_global(gptr)) : "memory")
#define CP_COMMIT()  asm volatile("cp.async.commit_group;" ::: "memory")

#define LDSM_X4(r0, r1, r2, r3, addr) \
    asm volatile("ldmatrix.sync.aligned.m8n8.x4.shared.b16 {%0,%1,%2,%3}, [%4];" \
                 : "=r"(r0), "=r"(r1), "=r"(r2), "=r"(r3) : "r"(addr))

#define LDSM_X4_T(r0, r1, r2, r3, addr) \
    asm volatile("ldmatrix.sync.aligned.m8n8.x4.trans.shared.b16 {%0,%1,%2,%3}, [%4];" \
                 : "=r"(r0), "=r"(r1), "=r"(r2), "=r"(r3) : "r"(addr))

#define MMA_F16(d, a, b) \
    asm volatile("mma.sync.aligned.m16n8k16.row.col.f32.f16.f16.f32 " \
                 "{%0,%1,%2,%3}, {%4,%5,%6,%7}, {%8,%9}, {%0,%1,%2,%3};" \
                 : "+f"((d)[0]), "+f"((d)[1]), "+f"((d)[2]), "+f"((d)[3]) \
                 : "r"((a)[0]), "r"((a)[1]), "r"((a)[2]), "r"((a)[3]), \
                   "r"((b)[0]), "r"((b)[1]))

#define SW128(off) ((off) ^ (((off) >> 3) & 0x70))

__device__ __forceinline__ float ex2f(float x) {
    float r;
    asm("ex2.approx.ftz.f32 %0, %1;" : "=f"(r) : "f"(x));
    return r;
}

__device__ __forceinline__ uint32_t ex2h2(uint32_t x) {
    uint32_t r;
    asm("ex2.approx.f16x2 %0, %1;" : "=r"(r) : "r"(x));
    return r;
}

__device__ __forceinline__ uint32_t pack_h2(float a, float b) {
    __half2 h = __floats2half2_rn(a, b);
    return *(uint32_t*)&h;
}

// ---------------------------------------------------------------------------
// fp32 -> fp16 conversion kernels
// ---------------------------------------------------------------------------
__global__ __launch_bounds__(256) void convX_kernel(const float4* __restrict__ x, int n4)
{
    uint32_t* dst = (uint32_t*)g_Xh;
    for (int i = blockIdx.x * blockDim.x + threadIdx.x; i < n4;
         i += gridDim.x * blockDim.x) {
        float4 v = x[i];
        dst[2 * i]     = pack_h2(v.x, v.y);
        dst[2 * i + 1] = pack_h2(v.z, v.w);
    }
}

__global__ __launch_bounds__(256) void convW_kernel(const float4* __restrict__ w0,
                                                    const float4* __restrict__ w1,
                                                    const float4* __restrict__ w2,
                                                    const float4* __restrict__ w3,
                                                    int n4)
{
    const int z = blockIdx.z;
    const float4* src = (z == 0) ? w0 : (z == 1) ? w1 : (z == 2) ? w2 : w3;
    uint32_t* dst = (uint32_t*)g_Wh[z];
    for (int i = blockIdx.x * blockDim.x + threadIdx.x; i < n4;
         i += gridDim.x * blockDim.x) {
        float4 v = src[i];
        dst[2 * i]     = pack_h2(v.x, v.y);
        dst[2 * i + 1] = pack_h2(v.z, v.w);
    }
}

// ---------------------------------------------------------------------------
// fp16 1-product HMMA GEMM body (unchanged — near its roof)
// ---------------------------------------------------------------------------
#define TILE_B   16384
#define STAGE_B  (2 * TILE_B)

__device__ __forceinline__ void gemm_body(const __half* __restrict__ Ah,
                                          const __half* __restrict__ Wh,
                                          float* __restrict__ Cf,
                                          __half* __restrict__ Ch,
                                          int mode, int mBase, int nBase,
                                          uint32_t sb)
{
    const int tid  = threadIdx.x;
    const int wid  = tid >> 5;
    const int lane = tid & 31;
    const int wm = wid & 3;
    const int wn = wid >> 2;
    const int l15   = lane & 15;
    const int khalf = ((lane >> 4) & 1) * 16;

    const char* srcs[2] = {
        (const char*)(Ah + (size_t)mBase * DM),
        (const char*)(Wh + (size_t)nBase * DM)
    };

    float acc[2][8][4];
#pragma unroll
    for (int mt = 0; mt < 2; mt++)
#pragma unroll
        for (int nt = 0; nt < 8; nt++)
#pragma unroll
            for (int r = 0; r < 4; r++) acc[mt][nt][r] = 0.0f;

    auto load_stage = [&](int ic, int buf) {
        const uint32_t stage = sb + buf * STAGE_B;
#pragma unroll
        for (int t = 0; t < 2; t++) {
            const char* src = srcs[t];
#pragma unroll
            for (int r = 0; r < 4; r++) {
                int unit = r * 256 + tid;
                int row  = unit >> 3;
                int c16  = unit & 7;
                const char* g = src + (size_t)row * (DM * 2) + ic * 128 + c16 * 16;
                uint32_t so = stage + t * TILE_B + SW128(row * 128 + c16 * 16);
                CP_ASYNC16(so, g);
            }
        }
        CP_COMMIT();
    };

    load_stage(0, 0);

    for (int ic = 0; ic < 16; ic++) {
        if (ic < 15) load_stage(ic + 1, (ic + 1) & 1);
        if (ic < 15) asm volatile("cp.async.wait_group 1;" ::: "memory");
        else         asm volatile("cp.async.wait_group 0;" ::: "memory");
        __syncthreads();

        const uint32_t stage = sb + (ic & 1) * STAGE_B;
        const uint32_t aB = stage;
        const uint32_t wB = stage + TILE_B;

#pragma unroll
        for (int ks = 0; ks < 4; ks++) {
            const int kb = ks * 32 + khalf;

            uint32_t ah[2][4];
#pragma unroll
            for (int mt = 0; mt < 2; mt++) {
                int row = wm * 32 + mt * 16 + l15;
                uint32_t off = SW128(row * 128 + kb);
                LDSM_X4(ah[mt][0], ah[mt][1], ah[mt][2], ah[mt][3], aB + off);
            }

            uint32_t bh[8][2];
#pragma unroll
            for (int nq = 0; nq < 4; nq++) {
                int row = wn * 64 + nq * 16 + l15;
                uint32_t off = SW128(row * 128 + kb);
                uint32_t r0, r1, r2, r3;
                LDSM_X4(r0, r1, r2, r3, wB + off);
                bh[2 * nq][0] = r0; bh[2 * nq][1] = r2;
                bh[2 * nq + 1][0] = r1; bh[2 * nq + 1][1] = r3;
            }

#pragma unroll
            for (int mt = 0; mt < 2; mt++)
#pragma unroll
                for (int nt = 0; nt < 8; nt++)
                    MMA_F16(acc[mt][nt], ah[mt], bh[nt]);
        }
        __syncthreads();
    }

    // epilogue
    const int groupID = lane >> 2;
    const int tg      = lane & 3;
#pragma unroll
    for (int mt = 0; mt < 2; mt++) {
#pragma unroll
        for (int half = 0; half < 2; half++) {
            int m = mBase + wm * 32 + mt * 16 + groupID + half * 8;
#pragma unroll
            for (int nt = 0; nt < 8; nt++) {
                int n = nBase + wn * 64 + nt * 8 + tg * 2;
                float f0 = acc[mt][nt][half * 2 + 0];
                float f1 = acc[mt][nt][half * 2 + 1];
                if (mode == 0) {
                    float2 v; v.x = f0; v.y = f1;
                    *(float2*)&Cf[(size_t)m * DM + n] = v;
                } else {
                    int b = m >> 11;
                    int s = m & 2047;
                    int h = n >> 6;
                    int d = n & 63;
                    size_t addr = ((size_t)((b * HEADS + h) * S_LEN) + s) * DH + d;
                    *(uint32_t*)&Ch[addr] = pack_h2(f0, f1);
                }
            }
        }
    }
}

__global__ __launch_bounds__(256, 2) void qkv_gemm()
{
    extern __shared__ __align__(1024) char smem[];
    const uint32_t sb = smem_to_u32(smem);
    const int z = blockIdx.z;
    __half* Ch = (z == 0) ? g_Qh : (z == 1) ? g_Kh : g_Vh;
    gemm_body(g_Xh, g_Wh[z], nullptr, Ch, 1,
              blockIdx.y * 128, blockIdx.x * 128, sb);
}

__global__ __launch_bounds__(256, 2) void out_gemm(float* __restrict__ Cf)
{
    extern __shared__ __align__(1024) char smem[];
    const uint32_t sb = smem_to_u32(smem);
    gemm_body(g_Ah, g_Wh[3], Cf, nullptr, 0,
              blockIdx.y * 128, blockIdx.x * 128, sb);
}

// ---------------------------------------------------------------------------
// HMMA flash attention — 4 warps x 32 q-rows (2x m16), 128 threads.
// K/V fragments reused across both m-tiles -> LDSM traffic per MMA halved.
// SMEM: Qh 16K | 2 stages x (Kh 8K | Vh 8K) = 48KB.
// ---------------------------------------------------------------------------
#define FS_QB    16384
#define FS_STAGE 16384
#define FS_TOTAL (FS_QB + 2 * FS_STAGE)   // 49152

__global__ __launch_bounds__(128, 2) void flash_mma_kernel()
{
    extern __shared__ __align__(1024) char smem[];
    const uint32_t sb = smem_to_u32(smem);
    const int tid  = threadIdx.x;
    const int wid  = tid >> 5;           // 0..3
    const int lane = tid & 31;
    const int g    = lane >> 2;
    const int tg   = lane & 3;
    const int l15  = lane & 15;
    const int khalf = ((lane >> 4) & 1) * 16;

    const int qt = (gridDim.x - 1) - blockIdx.x;   // heavy blocks first
    const int bh = blockIdx.y;
    const int qtBase = qt * 128;
    const int ktmax  = qt * 2 + 1;

    const size_t headBase = (size_t)bh * S_LEN * DH;

    // ---- load Q once (128 rows x 128B, 128 threads x 8 units) ----
    {
        const __half* qsrc = g_Qh + headBase + (size_t)qtBase * DH;
#pragma unroll
        for (int r = 0; r < 8; r++) {
            int unit = r * 128 + tid;     // 0..1023
            int row  = unit >> 3;         // 0..127
            int c16  = unit & 7;
            const char* gp = (const char*)(qsrc + (size_t)row * DH) + c16 * 16;
            uint32_t so = sb + SW128(row * 128 + c16 * 16);
            CP_ASYNC16(so, gp);
        }
        CP_COMMIT();
    }

    const __half* kvsrc[2] = { g_Kh + headBase, g_Vh + headBase };

    auto load_kv = [&](int kt, int buf) {
        const uint32_t st = sb + FS_QB + buf * FS_STAGE;
        const size_t kvoff = (size_t)kt * 64 * DH;
#pragma unroll
        for (int t = 0; t < 2; t++) {
            const __half* base = kvsrc[t] + kvoff;
#pragma unroll
            for (int r = 0; r < 4; r++) {
                int unit = r * 128 + tid;     // 0..511
                int row  = unit >> 3;         // 0..63
                int c16  = unit & 7;
                const char* gp = (const char*)(base + (size_t)row * DH) + c16 * 16;
                uint32_t so = st + t * 8192 + SW128(row * 128 + c16 * 16);
                CP_ASYNC16(so, gp);
            }
        }
        CP_COMMIT();
    };

    load_kv(0, 0);

    uint32_t qh[2][4][4];
    float o[2][8][4];
    float m_i[2][2] = { { -1e30f, -1e30f }, { -1e30f, -1e30f } };
    float l_p[2][2] = { { 0.0f, 0.0f }, { 0.0f, 0.0f } };
#pragma unroll
    for (int mt = 0; mt < 2; mt++)
#pragma unroll
        for (int dt = 0; dt < 8; dt++)
#pragma unroll
            for (int r = 0; r < 4; r++) o[mt][dt][r] = 0.0f;

    const float C1 = 0.18033688011112042f;    // log2(e) / sqrt(64)
    const __half2 c1h2 = __float2half2_rn(C1);

    for (int kt = 0; kt <= ktmax; kt++) {
        if (kt < ktmax) load_kv(kt + 1, (kt + 1) & 1);
        if (kt < ktmax) asm volatile("cp.async.wait_group 1;" ::: "memory");
        else            asm volatile("cp.async.wait_group 0;" ::: "memory");
        __syncthreads();

        if (kt == 0) {
#pragma unroll
            for (int mt = 0; mt < 2; mt++)
#pragma unroll
                for (int ks = 0; ks < 4; ks++) {
                    int row = wid * 32 + mt * 16 + l15;
                    uint32_t off = SW128(row * 128 + ks * 32 + khalf);
                    LDSM_X4(qh[mt][ks][0], qh[mt][ks][1], qh[mt][ks][2], qh[mt][ks][3],
                            sb + off);
                }
        }

        const uint32_t st  = sb + FS_QB + (kt & 1) * FS_STAGE;
        const uint32_t KhB = st;
        const uint32_t VhB = st + 8192;

        // ---- S = Q K^T (K fragments shared across both m-tiles) ----
        float sacc[2][8][4];
#pragma unroll
        for (int mt = 0; mt < 2; mt++)
#pragma unroll
            for (int nt = 0; nt < 8; nt++)
#pragma unroll
                for (int r = 0; r < 4; r++) sacc[mt][nt][r] = 0.0f;

#pragma unroll
        for (int ks = 0; ks < 4; ks++) {
            const int kb = ks * 32 + khalf;
            uint32_t kh[8][2];
#pragma unroll
            for (int nq = 0; nq < 4; nq++) {
                int row = nq * 16 + l15;
                uint32_t off = SW128(row * 128 + kb);
                uint32_t r0, r1, r2, r3;
                LDSM_X4(r0, r1, r2, r3, KhB + off);
                kh[2 * nq][0] = r0; kh[2 * nq][1] = r2;
                kh[2 * nq + 1][0] = r1; kh[2 * nq + 1][1] = r3;
            }
#pragma unroll
            for (int mt = 0; mt < 2; mt++)
#pragma unroll
                for (int nt = 0; nt < 8; nt++)
                    MMA_F16(sacc[mt][nt], qh[mt][ks], kh[nt]);
        }

        // ---- causal mask ----
        if (kt >= 2 * qt) {
            const int kcb = kt * 64;
#pragma unroll
            for (int mt = 0; mt < 2; mt++) {
                const int q0 = qtBase + wid * 32 + mt * 16 + g;
#pragma unroll
                for (int nt = 0; nt < 8; nt++) {
                    int kc = kcb + nt * 8 + tg * 2;
                    if (kc     > q0)     sacc[mt][nt][0] = -1e30f;
                    if (kc + 1 > q0)     sacc[mt][nt][1] = -1e30f;
                    if (kc     > q0 + 8) sacc[mt][nt][2] = -1e30f;
                    if (kc + 1 > q0 + 8) sacc[mt][nt][3] = -1e30f;
                }
            }
        }

        // ---- online softmax (fp16x2) ----
        uint32_t pp[2][2][8];
#pragma unroll
        for (int mt = 0; mt < 2; mt++) {
#pragma unroll
            for (int i = 0; i < 2; i++) {
                uint32_t th2[8];
#pragma unroll
                for (int nt = 0; nt < 8; nt++)
                    th2[nt] = pack_h2(sacc[mt][nt][2 * i], sacc[mt][nt][2 * i + 1]);

                __half2 mh = *(__half2*)&th2[0];
#pragma unroll
                for (int nt = 1; nt < 8; nt++)
                    mh = __hmax2(mh, *(__half2*)&th2[nt]);
                float mx = fmaxf(__low2float(mh), __high2float(mh));
                mx = fmaxf(mx, __shfl_xor_sync(0xffffffffu, mx, 1));
                mx = fmaxf(mx, __shfl_xor_sync(0xffffffffu, mx, 2));

                float mnew = fmaxf(m_i[mt][i], mx);
                float corr = ex2f((m_i[mt][i] - mnew) * C1);
                m_i[mt][i] = mnew;

                const __half2 bh2 = __float2half2_rn(-mnew * C1);
                __half2 hsum = __float2half2_rn(0.0f);
#pragma unroll
                for (int nt = 0; nt < 8; nt++) {
                    __half2 arg = __hfma2(*(__half2*)&th2[nt], c1h2, bh2);
                    uint32_t p = ex2h2(*(uint32_t*)&arg);
                    pp[mt][i][nt] = p;
                    hsum = __hadd2(hsum, *(__half2*)&p);
                }
                l_p[mt][i] = l_p[mt][i] * corr + __low2float(hsum) + __high2float(hsum);
#pragma unroll
                for (int dt = 0; dt < 8; dt++) {
                    o[mt][dt][2 * i]     *= corr;
                    o[mt][dt][2 * i + 1] *= corr;
                }
            }
        }

        // ---- P fragments ----
        uint32_t ph[2][4][4];
#pragma unroll
        for (int mt = 0; mt < 2; mt++)
#pragma unroll
            for (int ks = 0; ks < 4; ks++) {
                ph[mt][ks][0] = pp[mt][0][2 * ks];
                ph[mt][ks][1] = pp[mt][1][2 * ks];
                ph[mt][ks][2] = pp[mt][0][2 * ks + 1];
                ph[mt][ks][3] = pp[mt][1][2 * ks + 1];
            }

        // ---- O += P V (V fragments shared across both m-tiles) ----
#pragma unroll
        for (int ks = 0; ks < 4; ks++) {
            uint32_t vh[8][2];
#pragma unroll
            for (int dp = 0; dp < 4; dp++) {
                uint32_t off = SW128((ks * 16 + l15) * 128 + dp * 32 + khalf);
                uint32_t r0, r1, r2, r3;
                LDSM_X4_T(r0, r1, r2, r3, VhB + off);
                vh[2 * dp][0] = r0; vh[2 * dp][1] = r1;
                vh[2 * dp + 1][0] = r2; vh[2 * dp + 1][1] = r3;
            }
#pragma unroll
            for (int mt = 0; mt < 2; mt++)
#pragma unroll
                for (int dt = 0; dt < 8; dt++)
                    MMA_F16(o[mt][dt], ph[mt][ks], vh[dt]);
        }

        __syncthreads();
    }

    // ---- epilogue ----
    const int b = bh >> 4;
    const int h = bh & 15;
#pragma unroll
    for (int mt = 0; mt < 2; mt++) {
#pragma unroll
        for (int i = 0; i < 2; i++) {
            float l = l_p[mt][i];
            l += __shfl_xor_sync(0xffffffffu, l, 1);
            l += __shfl_xor_sync(0xffffffffu, l, 2);
            float inv = 1.0f / l;
            int srow = qtBase + wid * 32 + mt * 16 + g + 8 * i;
            size_t rowaddr = ((size_t)(b * S_LEN + srow)) * DM + h * 64;
#pragma unroll
            for (int dt = 0; dt < 8; dt++) {
                float f0 = o[mt][dt][2 * i]     * inv;
                float f1 = o[mt][dt][2 * i + 1] * inv;
                size_t addr = rowaddr + dt * 8 + tg * 2;
                *(uint32_t*)&g_Ah[addr] = pack_h2(f0, f1);
            }
        }
    }
}

// ---------------------------------------------------------------------------
// Launch
// ---------------------------------------------------------------------------
extern "C" void kernel_launch(void* const* d_in, const int* in_sizes, int n_in,
                              void* d_out, int out_size)
{
    const float* X  = (const float*)d_in[0];
    const float* WQ = (const float*)d_in[1];
    const float* WK = (const float*)d_in[2];
    const float* WV = (const float*)d_in[3];
    const float* WO = (const float*)d_in[4];
    float* out = (float*)d_out;

    const int smem_gemm = 2 * STAGE_B;   // 65536
    cudaFuncSetAttribute(qkv_gemm,
                         cudaFuncAttributeMaxDynamicSharedMemorySize, smem_gemm);
    cudaFuncSetAttribute(out_gemm,
                         cudaFuncAttributeMaxDynamicSharedMemorySize, smem_gemm);
    cudaFuncSetAttribute(flash_mma_kernel,
                         cudaFuncAttributeMaxDynamicSharedMemorySize, FS_TOTAL);

    convX_kernel<<<4096, 256>>>((const float4*)X, MROWS * DM / 4);
    convW_kernel<<<dim3(1024, 1, 4), 256>>>((const float4*)WQ, (const float4*)WK,
                                            (const float4*)WV, (const float4*)WO,
                                            DM * DM / 4);

    qkv_gemm<<<dim3(DM / 128, MROWS / 128, 3), 256, smem_gemm>>>();

    flash_mma_kernel<<<dim3(S_LEN / 128, BATCH * HEADS), 128, FS_TOTAL>>>();

    out_gemm<<<dim3(DM / 128, MROWS / 128), 256, smem_gemm>>>(out);
}